// round 7
// baseline (speedup 1.0000x reference)
#include <cuda_runtime.h>
#include <cuda_bf16.h>
#include <math.h>
#include <stdint.h>

#define B_  4
#define H_  16
#define LQ_ 512
#define LK_ 2048
#define DM_ 1024

#define XQ_ROW 0
#define XK_ROW 2048
#define XV_ROW (2048 + 8192)

// ---------------------------------------------------------------------------
// Scratch (device globals; no runtime allocation allowed)
// ---------------------------------------------------------------------------
__device__ __align__(16) __nv_bfloat16 g_wth[(size_t)4 * DM_ * DM_];  // W^T hi [mat][n][k]
__device__ __align__(16) __nv_bfloat16 g_wtl[(size_t)4 * DM_ * DM_];  // W^T lo
__device__ __align__(16) __nv_bfloat16 g_xh [(size_t)18432 * DM_];    // X hi [row][k]
__device__ __align__(16) __nv_bfloat16 g_xl [(size_t)18432 * DM_];    // X lo
__device__ __align__(16) uint32_t g_qh [(size_t)B_*H_*LQ_*32];        // q hi [b,h,l,dpair]
__device__ __align__(16) uint32_t g_ql [(size_t)B_*H_*LQ_*32];
__device__ __align__(16) uint32_t g_kh [(size_t)B_*H_*LK_*32];        // k hi [b,h,l,dpair]
__device__ __align__(16) uint32_t g_kl [(size_t)B_*H_*LK_*32];
__device__ __align__(16) __nv_bfloat16 g_vth[(size_t)B_*H_*64*LK_];   // V^T hi [b,h,d,key]
__device__ __align__(16) __nv_bfloat16 g_vtl[(size_t)B_*H_*64*LK_];   // V^T lo
__device__ __align__(16) uint32_t g_aoh[(size_t)B_*LQ_*512];          // attn out hi [row][dpair]
__device__ __align__(16) uint32_t g_aol[(size_t)B_*LQ_*512];
__device__ __align__(16) float    g_y  [(size_t)B_*LQ_*DM_];          // pre-LN

// ---------------------------------------------------------------------------
// helpers
// ---------------------------------------------------------------------------
__device__ __forceinline__ uint32_t packbf(float e, float o) {
    uint32_t r;
    asm("cvt.rn.bf16x2.f32 %0, %1, %2;" : "=r"(r) : "f"(o), "f"(e));
    return r;
}
__device__ __forceinline__ float lo16f(uint32_t h) { return __uint_as_float(h << 16); }
__device__ __forceinline__ float hi16f(uint32_t h) { return __uint_as_float(h & 0xffff0000u); }

__device__ __forceinline__ void split2(float x, float y, uint32_t& hi, uint32_t& lo) {
    hi = packbf(x, y);
    lo = packbf(x - lo16f(hi), y - hi16f(hi));
}
__device__ __forceinline__ void split1(float v, __nv_bfloat16& h, __nv_bfloat16& l) {
    h = __float2bfloat16(v);
    l = __float2bfloat16(v - __bfloat162float(h));
}

__device__ __forceinline__ void mma_bf16(float c[4],
                                         uint32_t a0, uint32_t a1, uint32_t a2, uint32_t a3,
                                         uint32_t b0, uint32_t b1)
{
    asm volatile(
        "mma.sync.aligned.m16n8k16.row.col.f32.bf16.bf16.f32 "
        "{%0,%1,%2,%3}, {%4,%5,%6,%7}, {%8,%9}, {%0,%1,%2,%3};"
        : "+f"(c[0]), "+f"(c[1]), "+f"(c[2]), "+f"(c[3])
        : "r"(a0), "r"(a1), "r"(a2), "r"(a3), "r"(b0), "r"(b1));
}

__device__ __forceinline__ void ldsm4(uint32_t& r0, uint32_t& r1, uint32_t& r2, uint32_t& r3,
                                      uint32_t addr)
{
    asm volatile("ldmatrix.sync.aligned.m8n8.x4.shared.b16 {%0,%1,%2,%3}, [%4];"
                 : "=r"(r0), "=r"(r1), "=r"(r2), "=r"(r3) : "r"(addr));
}

__device__ __forceinline__ uint32_t smem_u32(const void* p) {
    uint32_t a;
    asm("{ .reg .u64 t; cvta.to.shared.u64 t, %1; cvt.u32.u64 %0, t; }" : "=r"(a) : "l"(p));
    return a;
}

#define CP16(dst, src) \
    asm volatile("cp.async.cg.shared.global [%0], [%1], 16;" :: "r"(dst), "l"(src) : "memory")
#define CPCOMMIT() asm volatile("cp.async.commit_group;" ::: "memory")
#define CPWAIT1()  asm volatile("cp.async.wait_group 1;" ::: "memory")
#define CPWAIT0()  asm volatile("cp.async.wait_group 0;" ::: "memory")

// ---------------------------------------------------------------------------
// Pre-pass: X fp32 -> bf16 hi/lo
// ---------------------------------------------------------------------------
__global__ void convert_x(const float* __restrict__ src,
                          __nv_bfloat16* __restrict__ dh, __nv_bfloat16* __restrict__ dl)
{
    size_t t = (size_t)blockIdx.x * 256 + threadIdx.x;
    float4 v = ((const float4*)src)[t];
    uint32_t h0, l0, h1, l1;
    split2(v.x, v.y, h0, l0);
    split2(v.z, v.w, h1, l1);
    uint2 hh = {h0, h1}, ll = {l0, l1};
    ((uint2*)dh)[t] = hh;
    ((uint2*)dl)[t] = ll;
}

// Pre-pass: W [k][n] fp32 -> W^T [n][k] bf16 hi/lo
__global__ void convert_wt(const float* __restrict__ W,
                           __nv_bfloat16* __restrict__ th, __nv_bfloat16* __restrict__ tl)
{
    __shared__ float tile[64][65];
    const int n0 = blockIdx.x * 64, k0 = blockIdx.y * 64;
    const int tid = threadIdx.x;
    #pragma unroll
    for (int i = 0; i < 16; i++) {
        int idx = tid + i * 256;
        int r = idx >> 6, c = idx & 63;
        tile[r][c] = W[(size_t)(k0 + r) * DM_ + n0 + c];
    }
    __syncthreads();
    #pragma unroll
    for (int i = 0; i < 16; i++) {
        int idx = tid + i * 256;
        int nr = idx >> 6, kc = idx & 63;
        __nv_bfloat16 hb, lb;
        split1(tile[kc][nr], hb, lb);
        th[(size_t)(n0 + nr) * DM_ + k0 + kc] = hb;
        tl[(size_t)(n0 + nr) * DM_ + k0 + kc] = lb;
    }
}

// ---------------------------------------------------------------------------
// GEMM: CTA 128x128, BK=32, 256 thr (8 warps 2x4), warp 64x32. 3-pass bf16.
// Smem tiles as 8x8-bf16 (128B) matrix blocks; ldmatrix fragments; 2-stage cp.async.
// outMode: 0 -> g_qh/ql, 1 -> g_kh/kl, 2 -> g_vth/vtl (V^T), 3 -> g_y (+resid)
// ---------------------------------------------------------------------------
#define G_STG 32768
#define GEMM_SMEM (2 * G_STG)

__global__ __launch_bounds__(256, 2)
void gemm_ld(const __nv_bfloat16* __restrict__ Ah_g, const __nv_bfloat16* __restrict__ Al_g,
             const __nv_bfloat16* __restrict__ Bh_g, const __nv_bfloat16* __restrict__ Bl_g,
             const float* __restrict__ bias, const float* __restrict__ resid,
             int L, int outMode)
{
    extern __shared__ char smc[];
    const uint32_t sbase = smem_u32(smc);
    const int tid  = threadIdx.x;
    const int lane = tid & 31;
    const int w    = tid >> 5;
    const int row0 = blockIdx.y * 128;
    const int col0 = blockIdx.x * 128;

    const int wmb = (w >> 2) * 8;     // m block base (8-row units)
    const int wnb = (w & 3) * 4;      // n block base
    const int grp = lane >> 2;
    const int tg  = lane & 3;
    const int o   = lane >> 3;
    const int r   = lane & 7;

    const uint32_t aconst = r * 16 + (o & 1) * 512 + (o >> 1) * 128;
    const uint32_t bconst = r * 16 + (o >> 1) * 512 + (o & 1) * 128;

    float acc[4][4][4] = {};

    auto fill = [&](uint32_t sb, int k0) {
        #pragma unroll
        for (int i = 0; i < 2; i++) {
            int c = tid + i * 256;          // 0..511
            int m = c >> 2, cb = c & 3;
            uint32_t d = sb + (uint32_t)(((m >> 3) * 4 + cb) * 128 + (m & 7) * 16);
            CP16(d,         Ah_g + (size_t)(row0 + m) * DM_ + k0 + cb * 8);
            CP16(d + 8192,  Al_g + (size_t)(row0 + m) * DM_ + k0 + cb * 8);
            CP16(d + 16384, Bh_g + (size_t)(col0 + m) * DM_ + k0 + cb * 8);
            CP16(d + 24576, Bl_g + (size_t)(col0 + m) * DM_ + k0 + cb * 8);
        }
        CPCOMMIT();
    };

    fill(sbase, 0);

    for (int t = 0; t < 32; t++) {
        if (t + 1 < 32) fill(sbase + ((t + 1) & 1) * G_STG, (t + 1) * 32);
        if (t + 1 < 32) CPWAIT1(); else CPWAIT0();
        __syncthreads();

        const uint32_t sb = sbase + (t & 1) * G_STG;
        #pragma unroll
        for (int kt = 0; kt < 2; kt++) {
            uint32_t bh[4][2], bl[4][2];
            #pragma unroll
            for (int np = 0; np < 2; np++) {
                uint32_t aB = sb + 16384 + (wnb + 2 * np) * 512 + kt * 256 + bconst;
                ldsm4(bh[2*np][0], bh[2*np][1], bh[2*np+1][0], bh[2*np+1][1], aB);
                ldsm4(bl[2*np][0], bl[2*np][1], bl[2*np+1][0], bl[2*np+1][1], aB + 8192);
            }
            #pragma unroll
            for (int ms = 0; ms < 4; ms++) {
                uint32_t aA = sb + (wmb + 2 * ms) * 512 + kt * 256 + aconst;
                uint32_t ah0, ah1, ah2, ah3, al0, al1, al2, al3;
                ldsm4(ah0, ah1, ah2, ah3, aA);
                ldsm4(al0, al1, al2, al3, aA + 8192);
                #pragma unroll
                for (int nt = 0; nt < 4; nt++) {
                    mma_bf16(acc[ms][nt], ah0, ah1, ah2, ah3, bh[nt][0], bh[nt][1]);
                    mma_bf16(acc[ms][nt], ah0, ah1, ah2, ah3, bl[nt][0], bl[nt][1]);
                    mma_bf16(acc[ms][nt], al0, al1, al2, al3, bh[nt][0], bh[nt][1]);
                }
            }
        }
        __syncthreads();
    }

    // ---- epilogue ----
    const int wm = (w >> 2) * 64, wn = (w & 3) * 32;
    #pragma unroll
    for (int nt = 0; nt < 4; nt++) {
        const int gc = col0 + wn + nt * 8 + tg * 2;
        const float b0 = bias[gc], b1 = bias[gc + 1];
        #pragma unroll
        for (int m = 0; m < 4; m++) {
            int r0 = row0 + wm + m * 16 + grp;
            int r1 = r0 + 8;
            float v00 = acc[m][nt][0] + b0, v01 = acc[m][nt][1] + b1;
            float v10 = acc[m][nt][2] + b0, v11 = acc[m][nt][3] + b1;
            if (outMode == 3) {
                float2 rr0 = *(const float2*)&resid[(size_t)r0 * DM_ + gc];
                float2 rr1 = *(const float2*)&resid[(size_t)r1 * DM_ + gc];
                float2 o0 = {v00 + rr0.x, v01 + rr0.y};
                float2 o1 = {v10 + rr1.x, v11 + rr1.y};
                *(float2*)&g_y[(size_t)r0 * DM_ + gc] = o0;
                *(float2*)&g_y[(size_t)r1 * DM_ + gc] = o1;
            } else if (outMode == 2) {
                const int hh = gc >> 6, d = gc & 63;
                const int b0i = r0 / L, k0i = r0 % L;
                const int b1i = r1 / L, k1i = r1 % L;
                size_t base0 = (size_t)(b0i * H_ + hh) * 64;
                size_t base1 = (size_t)(b1i * H_ + hh) * 64;
                __nv_bfloat16 hb, lb;
                split1(v00, hb, lb); g_vth[(base0 + d)     * LK_ + k0i] = hb; g_vtl[(base0 + d)     * LK_ + k0i] = lb;
                split1(v01, hb, lb); g_vth[(base0 + d + 1) * LK_ + k0i] = hb; g_vtl[(base0 + d + 1) * LK_ + k0i] = lb;
                split1(v10, hb, lb); g_vth[(base1 + d)     * LK_ + k1i] = hb; g_vtl[(base1 + d)     * LK_ + k1i] = lb;
                split1(v11, hb, lb); g_vth[(base1 + d + 1) * LK_ + k1i] = hb; g_vtl[(base1 + d + 1) * LK_ + k1i] = lb;
            } else {
                uint32_t h0, l0u, h1, l1u;
                split2(v00, v01, h0, l0u);
                split2(v10, v11, h1, l1u);
                const int hh = gc >> 6, dp = (gc & 63) >> 1;
                const int b0i = r0 / L, ll0 = r0 % L;
                const int b1i = r1 / L, ll1 = r1 % L;
                uint32_t* oh = (outMode == 0) ? g_qh : g_kh;
                uint32_t* ol = (outMode == 0) ? g_ql : g_kl;
                size_t i0 = ((size_t)(b0i * H_ + hh) * L + ll0) * 32 + dp;
                size_t i1 = ((size_t)(b1i * H_ + hh) * L + ll1) * 32 + dp;
                oh[i0] = h0; ol[i0] = l0u;
                oh[i1] = h1; ol[i1] = l1u;
            }
        }
    }
}

// ---------------------------------------------------------------------------
// Flash attention: block (64q, h, b), 128 thr (4 warps, warp = 16 q rows).
// 8x8-matrix smem tiles + ldmatrix; Q fragments register-resident; 2-stage cp.async.
// ---------------------------------------------------------------------------
#define FQ_H 0
#define F_STG0 16384
#define F_STG 33024
#define FA_SMEM (16384 + 2 * 33024)

__global__ __launch_bounds__(128)
void flash_attn(const int* __restrict__ mask)
{
    extern __shared__ char smc[];
    const uint32_t sbase = smem_u32(smc);
    const int q0 = blockIdx.x * 64, h = blockIdx.y, b = blockIdx.z;
    const int tid  = threadIdx.x;
    const int lane = tid & 31;
    const int w    = tid >> 5;
    const int grp  = lane >> 2;
    const int tg   = lane & 3;
    const int o    = lane >> 3;
    const int r    = lane & 7;

    const size_t bh_off = (size_t)(b * H_ + h);
    const uint32_t* kh_g = g_kh + bh_off * LK_ * 32;
    const uint32_t* kl_g = g_kl + bh_off * LK_ * 32;
    const __nv_bfloat16* vh_g = g_vth + bh_off * 64 * LK_;
    const __nv_bfloat16* vl_g = g_vtl + bh_off * 64 * LK_;
    const int* mk_g = mask + b * LK_;

    // lane-constant LDSM offsets
    const uint32_t qconst = r * 16 + (o & 1) * 1024 + (o >> 1) * 128;   // A-type (rowblk stride 8 mats)
    const uint32_t kconst = r * 16 + (o >> 1) * 1024 + (o & 1) * 128;   // B-type

    // ---- prefetch Q (once) + stage 0 ----
    {
        const uint32_t* qh_g = g_qh + (bh_off * LQ_ + q0) * 32;
        const uint32_t* ql_g = g_ql + (bh_off * LQ_ + q0) * 32;
        #pragma unroll
        for (int i = 0; i < 4; i++) {
            int c = tid + i * 128;                 // 0..511
            int row = c >> 3, cb = c & 7;
            uint32_t d = sbase + FQ_H + (uint32_t)(((row >> 3) * 8 + cb) * 128 + (row & 7) * 16);
            CP16(d,        qh_g + (size_t)row * 32 + cb * 4);
            CP16(d + 8192, ql_g + (size_t)row * 32 + cb * 4);
        }
    }
    auto fill = [&](uint32_t sb, int k0) {
        #pragma unroll
        for (int i = 0; i < 4; i++) {
            int c = tid + i * 128;
            int row = c >> 3, cb = c & 7;
            uint32_t dm = (uint32_t)(((row >> 3) * 8 + cb) * 128 + (row & 7) * 16);
            CP16(sb + dm,         kh_g + (size_t)(k0 + row) * 32 + cb * 4);
            CP16(sb + dm + 8192,  kl_g + (size_t)(k0 + row) * 32 + cb * 4);
            CP16(sb + dm + 16384, vh_g + (size_t)row * LK_ + k0 + cb * 8);
            CP16(sb + dm + 24576, vl_g + (size_t)row * LK_ + k0 + cb * 8);
        }
        if (tid < 16) CP16(sb + 32768 + tid * 16, mk_g + k0 + tid * 4);
        CPCOMMIT();
    };
    fill(sbase + F_STG0, 0);

    uint32_t qfh[4][4], qfl[4][4];
    float oacc[8][4];
    #pragma unroll
    for (int nt = 0; nt < 8; nt++)
        #pragma unroll
        for (int j = 0; j < 4; j++) oacc[nt][j] = 0.f;
    float m0 = -1e30f, m1 = -1e30f, lsum0 = 0.f, lsum1 = 0.f;

    for (int t = 0; t < LK_ / 64; t++) {
        if (t + 1 < LK_ / 64) fill(sbase + F_STG0 + ((t + 1) & 1) * F_STG, (t + 1) * 64);
        if (t + 1 < LK_ / 64) CPWAIT1(); else CPWAIT0();
        __syncthreads();

        if (t == 0) {
            #pragma unroll
            for (int kt = 0; kt < 4; kt++) {
                uint32_t aQ = sbase + FQ_H + w * 2048 + kt * 256 + qconst;
                ldsm4(qfh[kt][0], qfh[kt][1], qfh[kt][2], qfh[kt][3], aQ);
                ldsm4(qfl[kt][0], qfl[kt][1], qfl[kt][2], qfl[kt][3], aQ + 8192);
            }
        }

        const uint32_t sb = sbase + F_STG0 + (t & 1) * F_STG;
        const int* msk = (const int*)(smc + (F_STG0 + (t & 1) * F_STG) + 32768);

        // ---- S = Q K^T ----
        float s[8][4];
        #pragma unroll
        for (int nt = 0; nt < 8; nt++)
            #pragma unroll
            for (int j = 0; j < 4; j++) s[nt][j] = 0.f;

        #pragma unroll
        for (int kt = 0; kt < 4; kt++) {
            #pragma unroll
            for (int np = 0; np < 4; np++) {
                uint32_t aK = sb + (2 * np) * 1024 + kt * 256 + kconst;
                uint32_t h0, h1, h2, h3, l0, l1, l2, l3;
                ldsm4(h0, h1, h2, h3, aK);
                ldsm4(l0, l1, l2, l3, aK + 8192);
                mma_bf16(s[2*np],   qfh[kt][0], qfh[kt][1], qfh[kt][2], qfh[kt][3], h0, h1);
                mma_bf16(s[2*np],   qfh[kt][0], qfh[kt][1], qfh[kt][2], qfh[kt][3], l0, l1);
                mma_bf16(s[2*np],   qfl[kt][0], qfl[kt][1], qfl[kt][2], qfl[kt][3], h0, h1);
                mma_bf16(s[2*np+1], qfh[kt][0], qfh[kt][1], qfh[kt][2], qfh[kt][3], h2, h3);
                mma_bf16(s[2*np+1], qfh[kt][0], qfh[kt][1], qfh[kt][2], qfh[kt][3], l2, l3);
                mma_bf16(s[2*np+1], qfl[kt][0], qfl[kt][1], qfl[kt][2], qfl[kt][3], h2, h3);
            }
        }

        // ---- online softmax ----
        const float scl = 0.125f;
        float rmax0 = -1e30f, rmax1 = -1e30f;
        #pragma unroll
        for (int nt = 0; nt < 8; nt++) {
            float mk0 = (msk[nt * 8 + 2 * tg]     == 0) ? -1e30f : 0.0f;
            float mk1 = (msk[nt * 8 + 2 * tg + 1] == 0) ? -1e30f : 0.0f;
            s[nt][0] = s[nt][0] * scl + mk0;
            s[nt][1] = s[nt][1] * scl + mk1;
            s[nt][2] = s[nt][2] * scl + mk0;
            s[nt][3] = s[nt][3] * scl + mk1;
            rmax0 = fmaxf(rmax0, fmaxf(s[nt][0], s[nt][1]));
            rmax1 = fmaxf(rmax1, fmaxf(s[nt][2], s[nt][3]));
        }
        rmax0 = fmaxf(rmax0, __shfl_xor_sync(0xffffffffu, rmax0, 1));
        rmax0 = fmaxf(rmax0, __shfl_xor_sync(0xffffffffu, rmax0, 2));
        rmax1 = fmaxf(rmax1, __shfl_xor_sync(0xffffffffu, rmax1, 1));
        rmax1 = fmaxf(rmax1, __shfl_xor_sync(0xffffffffu, rmax1, 2));

        float mn0 = fmaxf(m0, rmax0), mn1 = fmaxf(m1, rmax1);
        float c0 = __expf(m0 - mn0),  c1 = __expf(m1 - mn1);
        m0 = mn0; m1 = mn1;

        float sum0 = 0.f, sum1 = 0.f;
        #pragma unroll
        for (int nt = 0; nt < 8; nt++) {
            s[nt][0] = __expf(s[nt][0] - mn0);
            s[nt][1] = __expf(s[nt][1] - mn0);
            s[nt][2] = __expf(s[nt][2] - mn1);
            s[nt][3] = __expf(s[nt][3] - mn1);
            sum0 += s[nt][0] + s[nt][1];
            sum1 += s[nt][2] + s[nt][3];
        }
        sum0 += __shfl_xor_sync(0xffffffffu, sum0, 1);
        sum0 += __shfl_xor_sync(0xffffffffu, sum0, 2);
        sum1 += __shfl_xor_sync(0xffffffffu, sum1, 1);
        sum1 += __shfl_xor_sync(0xffffffffu, sum1, 2);
        lsum0 = lsum0 * c0 + sum0;
        lsum1 = lsum1 * c1 + sum1;

        #pragma unroll
        for (int nt = 0; nt < 8; nt++) {
            oacc[nt][0] *= c0; oacc[nt][1] *= c0;
            oacc[nt][2] *= c1; oacc[nt][3] *= c1;
        }

        // ---- O += P V ----
        #pragma unroll
        for (int kg = 0; kg < 4; kg++) {
            uint32_t ph0, ph1, ph2, ph3, pl0, pl1, pl2, pl3;
            split2(s[2*kg][0],   s[2*kg][1],   ph0, pl0);
            split2(s[2*kg][2],   s[2*kg][3],   ph1, pl1);
            split2(s[2*kg+1][0], s[2*kg+1][1], ph2, pl2);
            split2(s[2*kg+1][2], s[2*kg+1][3], ph3, pl3);
            #pragma unroll
            for (int np = 0; np < 4; np++) {
                uint32_t aV = sb + 16384 + (2 * np) * 1024 + kg * 256 + kconst;
                uint32_t h0, h1, h2, h3, l0, l1, l2, l3;
                ldsm4(h0, h1, h2, h3, aV);
                ldsm4(l0, l1, l2, l3, aV + 8192);
                mma_bf16(oacc[2*np],   ph0, ph1, ph2, ph3, h0, h1);
                mma_bf16(oacc[2*np],   ph0, ph1, ph2, ph3, l0, l1);
                mma_bf16(oacc[2*np],   pl0, pl1, pl2, pl3, h0, h1);
                mma_bf16(oacc[2*np+1], ph0, ph1, ph2, ph3, h2, h3);
                mma_bf16(oacc[2*np+1], ph0, ph1, ph2, ph3, l2, l3);
                mma_bf16(oacc[2*np+1], pl0, pl1, pl2, pl3, h2, h3);
            }
        }
        __syncthreads();
    }

    // ---- epilogue: packed hi/lo attention output ----
    float inv0 = 1.0f / lsum0, inv1 = 1.0f / lsum1;
    int qr0 = q0 + w * 16 + grp;
    int qr1 = qr0 + 8;
    size_t r0base = ((size_t)b * LQ_ + qr0) * 512 + h * 32;
    size_t r1base = ((size_t)b * LQ_ + qr1) * 512 + h * 32;
    #pragma unroll
    for (int nt = 0; nt < 8; nt++) {
        int dp = nt * 4 + tg;
        uint32_t hh, ll;
        split2(oacc[nt][0] * inv0, oacc[nt][1] * inv0, hh, ll);
        g_aoh[r0base + dp] = hh;
        g_aol[r0base + dp] = ll;
        split2(oacc[nt][2] * inv1, oacc[nt][3] * inv1, hh, ll);
        g_aoh[r1base + dp] = hh;
        g_aol[r1base + dp] = ll;
    }
}

// ---------------------------------------------------------------------------
// LayerNorm per row of g_y
// ---------------------------------------------------------------------------
__global__ void layernorm_kernel(const float* __restrict__ gamma,
                                 const float* __restrict__ beta,
                                 float* __restrict__ out)
{
    const int row = blockIdx.x;
    const int tid = threadIdx.x;
    __shared__ float red[256];

    const float* yr = g_y + (size_t)row * DM_;
    float4 xv = *(const float4*)(yr + tid * 4);

    float s = xv.x + xv.y + xv.z + xv.w;
    red[tid] = s; __syncthreads();
    #pragma unroll
    for (int st = 128; st > 0; st >>= 1) {
        if (tid < st) red[tid] += red[tid + st];
        __syncthreads();
    }
    float mean = red[0] * (1.0f / DM_);
    __syncthreads();

    float dx = xv.x - mean, dy = xv.y - mean, dz = xv.z - mean, dw = xv.w - mean;
    float sq = dx * dx + dy * dy + dz * dz + dw * dw;
    red[tid] = sq; __syncthreads();
    #pragma unroll
    for (int st = 128; st > 0; st >>= 1) {
        if (tid < st) red[tid] += red[tid + st];
        __syncthreads();
    }
    float rstd = rsqrtf(red[0] * (1.0f / DM_) + 1e-5f);

    int n = tid * 4;
    float4 ov;
    ov.x = dx * rstd * gamma[n]     + beta[n];
    ov.y = dy * rstd * gamma[n + 1] + beta[n + 1];
    ov.z = dz * rstd * gamma[n + 2] + beta[n + 2];
    ov.w = dw * rstd * gamma[n + 3] + beta[n + 3];
    *(float4*)(out + (size_t)row * DM_ + n) = ov;
}

// ---------------------------------------------------------------------------
extern "C" void kernel_launch(void* const* d_in, const int* in_sizes, int n_in,
                              void* d_out, int out_size)
{
    const float* Q    = (const float*)d_in[0];
    const float* K    = (const float*)d_in[1];
    const float* V    = (const float*)d_in[2];
    /* d_in[3] = node_num (unused) */
    const int*   mask = (const int*)  d_in[4];
    const float* Wq   = (const float*)d_in[5];
    const float* bq   = (const float*)d_in[6];
    const float* Wk   = (const float*)d_in[7];
    const float* bk   = (const float*)d_in[8];
    const float* Wv   = (const float*)d_in[9];
    const float* bv   = (const float*)d_in[10];
    const float* Wo   = (const float*)d_in[11];
    const float* bo   = (const float*)d_in[12];
    const float* gamma= (const float*)d_in[13];
    const float* beta = (const float*)d_in[14];
    float* out = (float*)d_out;

    cudaFuncSetAttribute(gemm_ld,    cudaFuncAttributeMaxDynamicSharedMemorySize, GEMM_SMEM);
    cudaFuncSetAttribute(flash_attn, cudaFuncAttributeMaxDynamicSharedMemorySize, FA_SMEM);

    __nv_bfloat16 *wth, *wtl, *xh, *xl;
    uint32_t *aoh, *aol;
    cudaGetSymbolAddress((void**)&wth, g_wth);
    cudaGetSymbolAddress((void**)&wtl, g_wtl);
    cudaGetSymbolAddress((void**)&xh,  g_xh);
    cudaGetSymbolAddress((void**)&xl,  g_xl);
    cudaGetSymbolAddress((void**)&aoh, g_aoh);
    cudaGetSymbolAddress((void**)&aol, g_aol);

    const size_t WS = (size_t)DM_ * DM_;

    // ---- pre-pass conversions ----
    convert_wt<<<dim3(16, 16), 256>>>(Wq, wth + 0 * WS, wtl + 0 * WS);
    convert_wt<<<dim3(16, 16), 256>>>(Wk, wth + 1 * WS, wtl + 1 * WS);
    convert_wt<<<dim3(16, 16), 256>>>(Wv, wth + 2 * WS, wtl + 2 * WS);
    convert_wt<<<dim3(16, 16), 256>>>(Wo, wth + 3 * WS, wtl + 3 * WS);
    convert_x<<<2048, 256>>>(Q, xh + (size_t)XQ_ROW * DM_, xl + (size_t)XQ_ROW * DM_);
    convert_x<<<8192, 256>>>(K, xh + (size_t)XK_ROW * DM_, xl + (size_t)XK_ROW * DM_);
    convert_x<<<8192, 256>>>(V, xh + (size_t)XV_ROW * DM_, xl + (size_t)XV_ROW * DM_);

    // ---- projections ----
    gemm_ld<<<dim3(8, 16), 256, GEMM_SMEM>>>(xh + (size_t)XQ_ROW * DM_, xl + (size_t)XQ_ROW * DM_,
                                             wth + 0 * WS, wtl + 0 * WS, bq, nullptr, LQ_, 0);
    gemm_ld<<<dim3(8, 64), 256, GEMM_SMEM>>>(xh + (size_t)XK_ROW * DM_, xl + (size_t)XK_ROW * DM_,
                                             wth + 1 * WS, wtl + 1 * WS, bk, nullptr, LK_, 1);
    gemm_ld<<<dim3(8, 64), 256, GEMM_SMEM>>>(xh + (size_t)XV_ROW * DM_, xl + (size_t)XV_ROW * DM_,
                                             wth + 2 * WS, wtl + 2 * WS, bv, nullptr, LK_, 2);

    // ---- attention ----
    flash_attn<<<dim3(LQ_ / 64, H_, B_), 128, FA_SMEM>>>(mask);

    // ---- output projection + residual ----
    gemm_ld<<<dim3(8, 16), 256, GEMM_SMEM>>>((const __nv_bfloat16*)aoh, (const __nv_bfloat16*)aol,
                                             wth + 3 * WS, wtl + 3 * WS, bo, Q, LQ_, 3);

    // ---- layernorm ----
    layernorm_kernel<<<B_ * LQ_, 256>>>(gamma, beta, out);
}

// round 8
// speedup vs baseline: 1.9796x; 1.9796x over previous
#include <cuda_runtime.h>
#include <cuda_fp16.h>
#include <math.h>
#include <stdint.h>

#define B_  4
#define H_  16
#define LQ_ 512
#define LK_ 2048
#define DM_ 1024

#define XQ_ROW 0
#define XK_ROW 2048
#define XV_ROW (2048 + 8192)

// ---------------------------------------------------------------------------
// Scratch (device globals; no runtime allocation allowed)
// ---------------------------------------------------------------------------
__device__ __align__(16) __half    g_wt [(size_t)4 * DM_ * DM_];     // W^T [mat][n][k] fp16
__device__ __align__(16) __half    g_x  [(size_t)18432 * DM_];       // X fp16 [row][k]
__device__ __align__(16) uint32_t  g_q  [(size_t)B_*H_*LQ_*32];      // q [b,h,l,dpair] half2
__device__ __align__(16) uint32_t  g_k  [(size_t)B_*H_*LK_*32];      // k [b,h,l,dpair] half2
__device__ __align__(16) __half    g_vt [(size_t)B_*H_*64*LK_];      // V^T [b,h,d,key] fp16
__device__ __align__(16) uint32_t  g_ao [(size_t)B_*LQ_*512];        // attn out [row][dpair] half2
__device__ __align__(16) float     g_y  [(size_t)B_*LQ_*DM_];        // pre-LN

// ---------------------------------------------------------------------------
// helpers
// ---------------------------------------------------------------------------
__device__ __forceinline__ uint32_t packh(float e, float o) {
    uint32_t r;
    asm("cvt.rn.f16x2.f32 %0, %1, %2;" : "=r"(r) : "f"(o), "f"(e));
    return r;
}

__device__ __forceinline__ void mma_f16(float c[4],
                                        uint32_t a0, uint32_t a1, uint32_t a2, uint32_t a3,
                                        uint32_t b0, uint32_t b1)
{
    asm volatile(
        "mma.sync.aligned.m16n8k16.row.col.f32.f16.f16.f32 "
        "{%0,%1,%2,%3}, {%4,%5,%6,%7}, {%8,%9}, {%0,%1,%2,%3};"
        : "+f"(c[0]), "+f"(c[1]), "+f"(c[2]), "+f"(c[3])
        : "r"(a0), "r"(a1), "r"(a2), "r"(a3), "r"(b0), "r"(b1));
}

// ---------------------------------------------------------------------------
// Pre-pass: X fp32 -> fp16
// ---------------------------------------------------------------------------
__global__ void convert_x(const float* __restrict__ src, __half* __restrict__ dst)
{
    size_t t = (size_t)blockIdx.x * 256 + threadIdx.x;
    float4 v = ((const float4*)src)[t];
    uint2 p;
    p.x = packh(v.x, v.y);
    p.y = packh(v.z, v.w);
    ((uint2*)dst)[t] = p;
}

// Pre-pass: W [k][n] fp32 -> W^T [n][k] fp16 (tiled transpose)
__global__ void convert_wt(const float* __restrict__ W, __half* __restrict__ T)
{
    __shared__ float tile[64][65];
    const int n0 = blockIdx.x * 64, k0 = blockIdx.y * 64;
    const int tid = threadIdx.x;
    #pragma unroll
    for (int i = 0; i < 16; i++) {
        int idx = tid + i * 256;
        int r = idx >> 6, c = idx & 63;
        tile[r][c] = W[(size_t)(k0 + r) * DM_ + n0 + c];
    }
    __syncthreads();
    #pragma unroll
    for (int i = 0; i < 16; i++) {
        int idx = tid + i * 256;
        int nr = idx >> 6, kc = idx & 63;
        T[(size_t)(n0 + nr) * DM_ + k0 + kc] = __float2half(tile[kc][nr]);
    }
}

// ---------------------------------------------------------------------------
// fp16 single-pass GEMM: CTA 128x128, BK=32 (16 kpairs), 256 thr (8 warps 2x4),
// warp tile 64x32. Smem: A and B both [row][16 kpairs u32] stride 20.
// outMode: 0 -> g_q, 1 -> g_k ([b,h,l,dpair]), 2 -> g_vt (V^T), 3 -> g_y (+resid)
// ---------------------------------------------------------------------------
#define GS_A 0
#define GS_B (128 * 20)
#define GEMM_SMEM (2 * 128 * 20 * 4)

__global__ __launch_bounds__(256, 2)
void gemm_h(const __half* __restrict__ A_g, const __half* __restrict__ B_g,
            const float* __restrict__ bias, const float* __restrict__ resid,
            int L, int outMode)
{
    extern __shared__ uint32_t sm[];
    uint32_t* As = sm + GS_A;
    uint32_t* Bs = sm + GS_B;

    const uint32_t* a32 = (const uint32_t*)A_g;
    const uint32_t* b32 = (const uint32_t*)B_g;

    const int row0 = blockIdx.y * 128;
    const int col0 = blockIdx.x * 128;
    const int tid  = threadIdx.x;
    const int lane = tid & 31;
    const int w    = tid >> 5;
    const int wm   = (w >> 2) * 64;
    const int wn   = (w & 3) * 32;
    const int grp  = lane >> 2;
    const int tg   = lane & 3;

    float acc[4][4][4] = {};

    const int fm = tid >> 1;            // 0..127
    const int fo = (tid & 1) * 8;       // u32 offset {0,8}

    for (int kp0 = 0; kp0 < DM_ / 2; kp0 += 16) {
        // ---- fill tiles: [128 rows][16 kpairs] ----
        {
            const size_t ga = (size_t)(row0 + fm) * 512 + kp0 + fo;
            const size_t gb = (size_t)(col0 + fm) * 512 + kp0 + fo;
            *(uint4*)&As[fm * 20 + fo]     = *(const uint4*)&a32[ga];
            *(uint4*)&As[fm * 20 + fo + 4] = *(const uint4*)&a32[ga + 4];
            *(uint4*)&Bs[fm * 20 + fo]     = *(const uint4*)&b32[gb];
            *(uint4*)&Bs[fm * 20 + fo + 4] = *(const uint4*)&b32[gb + 4];
        }
        __syncthreads();

        #pragma unroll
        for (int kt = 0; kt < 2; kt++) {
            const int kb = kt * 8;
            uint32_t bf[4][2];
            #pragma unroll
            for (int nt = 0; nt < 4; nt++) {
                int cc = wn + nt * 8 + grp;
                bf[nt][0] = Bs[cc * 20 + kb + tg];
                bf[nt][1] = Bs[cc * 20 + kb + tg + 4];
            }
            #pragma unroll
            for (int m = 0; m < 4; m++) {
                int r = wm + m * 16 + grp;
                uint32_t a0 = As[r * 20 + kb + tg];
                uint32_t a1 = As[(r + 8) * 20 + kb + tg];
                uint32_t a2 = As[r * 20 + kb + tg + 4];
                uint32_t a3 = As[(r + 8) * 20 + kb + tg + 4];
                #pragma unroll
                for (int nt = 0; nt < 4; nt++)
                    mma_f16(acc[m][nt], a0, a1, a2, a3, bf[nt][0], bf[nt][1]);
            }
        }
        __syncthreads();
    }

    // ---- epilogue ----
    #pragma unroll
    for (int nt = 0; nt < 4; nt++) {
        const int gc = col0 + wn + nt * 8 + tg * 2;
        const float b0 = bias[gc], b1 = bias[gc + 1];
        #pragma unroll
        for (int m = 0; m < 4; m++) {
            int r0 = row0 + wm + m * 16 + grp;
            int r1 = r0 + 8;
            float v00 = acc[m][nt][0] + b0, v01 = acc[m][nt][1] + b1;
            float v10 = acc[m][nt][2] + b0, v11 = acc[m][nt][3] + b1;
            if (outMode == 3) {
                float2 rr0 = *(const float2*)&resid[(size_t)r0 * DM_ + gc];
                float2 rr1 = *(const float2*)&resid[(size_t)r1 * DM_ + gc];
                float2 o0 = {v00 + rr0.x, v01 + rr0.y};
                float2 o1 = {v10 + rr1.x, v11 + rr1.y};
                *(float2*)&g_y[(size_t)r0 * DM_ + gc] = o0;
                *(float2*)&g_y[(size_t)r1 * DM_ + gc] = o1;
            } else if (outMode == 2) {
                const int hh = gc >> 6, d = gc & 63;
                const int b0i = r0 / L, k0i = r0 % L;
                const int b1i = r1 / L, k1i = r1 % L;
                size_t base0 = (size_t)(b0i * H_ + hh) * 64;
                size_t base1 = (size_t)(b1i * H_ + hh) * 64;
                g_vt[(base0 + d)     * LK_ + k0i] = __float2half(v00);
                g_vt[(base0 + d + 1) * LK_ + k0i] = __float2half(v01);
                g_vt[(base1 + d)     * LK_ + k1i] = __float2half(v10);
                g_vt[(base1 + d + 1) * LK_ + k1i] = __float2half(v11);
            } else {
                const int hh = gc >> 6, dp = (gc & 63) >> 1;
                const int b0i = r0 / L, ll0 = r0 % L;
                const int b1i = r1 / L, ll1 = r1 % L;
                uint32_t* oq = (outMode == 0) ? g_q : g_k;
                oq[((size_t)(b0i * H_ + hh) * L + ll0) * 32 + dp] = packh(v00, v01);
                oq[((size_t)(b1i * H_ + hh) * L + ll1) * 32 + dp] = packh(v10, v11);
            }
        }
    }
}

// ---------------------------------------------------------------------------
// fp16 flash attention: block (64q, h, b), 128 thr (4 warps, warp = 16 q rows).
// Smem (u32 = half2): Q [64 q][32 dpair] s36; K [64 key][32 dpair] s36;
// V [64 d][32 keypair] s36. Q fragments hoisted to registers.
// ---------------------------------------------------------------------------
#define FS_Q 0
#define FS_K (64 * 36)
#define FS_V (2 * 64 * 36)
#define FS_MSK (3 * 64 * 36)
#define FA_SMEM ((FS_MSK + 64) * 4)

__global__ __launch_bounds__(128)
void flash_attn(const int* __restrict__ mask)
{
    extern __shared__ uint32_t sm[];
    uint32_t* Qs = sm + FS_Q;
    uint32_t* Ks = sm + FS_K;
    uint32_t* Vs = sm + FS_V;
    float*   msk = (float*)(sm + FS_MSK);

    const int q0 = blockIdx.x * 64, h = blockIdx.y, b = blockIdx.z;
    const int tid  = threadIdx.x;
    const int lane = tid & 31;
    const int w    = tid >> 5;
    const int grp  = lane >> 2;
    const int tg   = lane & 3;

    const size_t bh_off = (size_t)(b * H_ + h);
    const uint32_t* kq_g = g_k + bh_off * LK_ * 32;
    const uint32_t* vt32 = (const uint32_t*)(g_vt + bh_off * 64 * LK_);

    // ---- load Q tile once ----
    {
        const uint32_t* qg = g_q + (bh_off * LQ_ + q0) * 32;
        int q = tid >> 1, half = (tid & 1) * 16;
        #pragma unroll
        for (int i = 0; i < 4; i++)
            *(uint4*)&Qs[q * 36 + half + i * 4] = *(const uint4*)&qg[(size_t)q * 32 + half + i * 4];
    }
    __syncthreads();

    // ---- Q fragments (registers for whole mainloop) ----
    uint32_t qf[4][4];
    {
        const int r = w * 16 + grp;
        #pragma unroll
        for (int kt = 0; kt < 4; kt++) {
            const int kb = kt * 8;
            qf[kt][0] = Qs[r * 36 + kb + tg];
            qf[kt][1] = Qs[(r + 8) * 36 + kb + tg];
            qf[kt][2] = Qs[r * 36 + kb + tg + 4];
            qf[kt][3] = Qs[(r + 8) * 36 + kb + tg + 4];
        }
    }

    float oacc[8][4];
    #pragma unroll
    for (int nt = 0; nt < 8; nt++)
        #pragma unroll
        for (int j = 0; j < 4; j++) oacc[nt][j] = 0.f;
    float m0 = -1e30f, m1 = -1e30f, lsum0 = 0.f, lsum1 = 0.f;

    const int fr = tid >> 1, fh = (tid & 1) * 16;

    for (int t = 0; t < LK_ / 64; t++) {
        const int k0 = t * 64;
        __syncthreads();
        // K tile: [key][dpair] coalesced
        #pragma unroll
        for (int i = 0; i < 4; i++)
            *(uint4*)&Ks[fr * 36 + fh + i * 4] =
                *(const uint4*)&kq_g[(size_t)(k0 + fr) * 32 + fh + i * 4];
        // V tile: [d][keypair] coalesced from V^T rows
        #pragma unroll
        for (int i = 0; i < 4; i++)
            *(uint4*)&Vs[fr * 36 + fh + i * 4] =
                *(const uint4*)&vt32[(size_t)fr * (LK_ / 2) + (k0 >> 1) + fh + i * 4];
        if (tid < 64) msk[tid] = (mask[b * LK_ + k0 + tid] == 0) ? -1e30f : 0.0f;
        __syncthreads();

        // ---- S = Q K^T ----
        float s[8][4];
        #pragma unroll
        for (int nt = 0; nt < 8; nt++)
            #pragma unroll
            for (int j = 0; j < 4; j++) s[nt][j] = 0.f;

        #pragma unroll
        for (int kt = 0; kt < 4; kt++) {
            const int kb = kt * 8;
            #pragma unroll
            for (int nt = 0; nt < 8; nt++) {
                int cc = nt * 8 + grp;
                uint32_t b0 = Ks[cc * 36 + kb + tg];
                uint32_t b1 = Ks[cc * 36 + kb + tg + 4];
                mma_f16(s[nt], qf[kt][0], qf[kt][1], qf[kt][2], qf[kt][3], b0, b1);
            }
        }

        // ---- online softmax ----
        const float scl = 0.125f;
        float rmax0 = -1e30f, rmax1 = -1e30f;
        #pragma unroll
        for (int nt = 0; nt < 8; nt++) {
            float mk0 = msk[nt * 8 + 2 * tg];
            float mk1 = msk[nt * 8 + 2 * tg + 1];
            s[nt][0] = s[nt][0] * scl + mk0;
            s[nt][1] = s[nt][1] * scl + mk1;
            s[nt][2] = s[nt][2] * scl + mk0;
            s[nt][3] = s[nt][3] * scl + mk1;
            rmax0 = fmaxf(rmax0, fmaxf(s[nt][0], s[nt][1]));
            rmax1 = fmaxf(rmax1, fmaxf(s[nt][2], s[nt][3]));
        }
        rmax0 = fmaxf(rmax0, __shfl_xor_sync(0xffffffffu, rmax0, 1));
        rmax0 = fmaxf(rmax0, __shfl_xor_sync(0xffffffffu, rmax0, 2));
        rmax1 = fmaxf(rmax1, __shfl_xor_sync(0xffffffffu, rmax1, 1));
        rmax1 = fmaxf(rmax1, __shfl_xor_sync(0xffffffffu, rmax1, 2));

        float mn0 = fmaxf(m0, rmax0), mn1 = fmaxf(m1, rmax1);
        float c0 = __expf(m0 - mn0),  c1 = __expf(m1 - mn1);
        m0 = mn0; m1 = mn1;

        float sum0 = 0.f, sum1 = 0.f;
        #pragma unroll
        for (int nt = 0; nt < 8; nt++) {
            s[nt][0] = __expf(s[nt][0] - mn0);
            s[nt][1] = __expf(s[nt][1] - mn0);
            s[nt][2] = __expf(s[nt][2] - mn1);
            s[nt][3] = __expf(s[nt][3] - mn1);
            sum0 += s[nt][0] + s[nt][1];
            sum1 += s[nt][2] + s[nt][3];
        }
        sum0 += __shfl_xor_sync(0xffffffffu, sum0, 1);
        sum0 += __shfl_xor_sync(0xffffffffu, sum0, 2);
        sum1 += __shfl_xor_sync(0xffffffffu, sum1, 1);
        sum1 += __shfl_xor_sync(0xffffffffu, sum1, 2);
        lsum0 = lsum0 * c0 + sum0;
        lsum1 = lsum1 * c1 + sum1;

        #pragma unroll
        for (int nt = 0; nt < 8; nt++) {
            oacc[nt][0] *= c0; oacc[nt][1] *= c0;
            oacc[nt][2] *= c1; oacc[nt][3] *= c1;
        }

        // ---- O += P V ----
        #pragma unroll
        for (int kg = 0; kg < 4; kg++) {
            uint32_t pa0 = packh(s[2*kg][0],   s[2*kg][1]);
            uint32_t pa1 = packh(s[2*kg][2],   s[2*kg][3]);
            uint32_t pa2 = packh(s[2*kg+1][0], s[2*kg+1][1]);
            uint32_t pa3 = packh(s[2*kg+1][2], s[2*kg+1][3]);
            const int kb = kg * 8;
            #pragma unroll
            for (int nt = 0; nt < 8; nt++) {
                int cc = nt * 8 + grp;
                uint32_t b0 = Vs[cc * 36 + kb + tg];
                uint32_t b1 = Vs[cc * 36 + kb + tg + 4];
                mma_f16(oacc[nt], pa0, pa1, pa2, pa3, b0, b1);
            }
        }
    }

    // ---- epilogue: packed fp16 attention output ----
    float inv0 = 1.0f / lsum0, inv1 = 1.0f / lsum1;
    int qr0 = q0 + w * 16 + grp;
    int qr1 = qr0 + 8;
    size_t r0base = ((size_t)b * LQ_ + qr0) * 512 + h * 32;
    size_t r1base = ((size_t)b * LQ_ + qr1) * 512 + h * 32;
    #pragma unroll
    for (int nt = 0; nt < 8; nt++) {
        int dp = nt * 4 + tg;
        g_ao[r0base + dp] = packh(oacc[nt][0] * inv0, oacc[nt][1] * inv0);
        g_ao[r1base + dp] = packh(oacc[nt][2] * inv1, oacc[nt][3] * inv1);
    }
}

// ---------------------------------------------------------------------------
// LayerNorm per row of g_y
// ---------------------------------------------------------------------------
__global__ void layernorm_kernel(const float* __restrict__ gamma,
                                 const float* __restrict__ beta,
                                 float* __restrict__ out)
{
    const int row = blockIdx.x;
    const int tid = threadIdx.x;
    __shared__ float red[256];

    const float* yr = g_y + (size_t)row * DM_;
    float4 xv = *(const float4*)(yr + tid * 4);

    float s = xv.x + xv.y + xv.z + xv.w;
    red[tid] = s; __syncthreads();
    #pragma unroll
    for (int st = 128; st > 0; st >>= 1) {
        if (tid < st) red[tid] += red[tid + st];
        __syncthreads();
    }
    float mean = red[0] * (1.0f / DM_);
    __syncthreads();

    float dx = xv.x - mean, dy = xv.y - mean, dz = xv.z - mean, dw = xv.w - mean;
    float sq = dx * dx + dy * dy + dz * dz + dw * dw;
    red[tid] = sq; __syncthreads();
    #pragma unroll
    for (int st = 128; st > 0; st >>= 1) {
        if (tid < st) red[tid] += red[tid + st];
        __syncthreads();
    }
    float rstd = rsqrtf(red[0] * (1.0f / DM_) + 1e-5f);

    int n = tid * 4;
    float4 ov;
    ov.x = dx * rstd * gamma[n]     + beta[n];
    ov.y = dy * rstd * gamma[n + 1] + beta[n + 1];
    ov.z = dz * rstd * gamma[n + 2] + beta[n + 2];
    ov.w = dw * rstd * gamma[n + 3] + beta[n + 3];
    *(float4*)(out + (size_t)row * DM_ + n) = ov;
}

// ---------------------------------------------------------------------------
extern "C" void kernel_launch(void* const* d_in, const int* in_sizes, int n_in,
                              void* d_out, int out_size)
{
    const float* Q    = (const float*)d_in[0];
    const float* K    = (const float*)d_in[1];
    const float* V    = (const float*)d_in[2];
    /* d_in[3] = node_num (unused) */
    const int*   mask = (const int*)  d_in[4];
    const float* Wq   = (const float*)d_in[5];
    const float* bq   = (const float*)d_in[6];
    const float* Wk   = (const float*)d_in[7];
    const float* bk   = (const float*)d_in[8];
    const float* Wv   = (const float*)d_in[9];
    const float* bv   = (const float*)d_in[10];
    const float* Wo   = (const float*)d_in[11];
    const float* bo   = (const float*)d_in[12];
    const float* gamma= (const float*)d_in[13];
    const float* beta = (const float*)d_in[14];
    float* out = (float*)d_out;

    cudaFuncSetAttribute(gemm_h,     cudaFuncAttributeMaxDynamicSharedMemorySize, GEMM_SMEM);
    cudaFuncSetAttribute(flash_attn, cudaFuncAttributeMaxDynamicSharedMemorySize, FA_SMEM);

    __half *wt, *x;
    uint32_t *ao;
    cudaGetSymbolAddress((void**)&wt, g_wt);
    cudaGetSymbolAddress((void**)&x,  g_x);
    cudaGetSymbolAddress((void**)&ao, g_ao);

    const size_t WS = (size_t)DM_ * DM_;

    // ---- pre-pass conversions ----
    convert_wt<<<dim3(16, 16), 256>>>(Wq, wt + 0 * WS);
    convert_wt<<<dim3(16, 16), 256>>>(Wk, wt + 1 * WS);
    convert_wt<<<dim3(16, 16), 256>>>(Wv, wt + 2 * WS);
    convert_wt<<<dim3(16, 16), 256>>>(Wo, wt + 3 * WS);
    convert_x<<<2048, 256>>>(Q, x + (size_t)XQ_ROW * DM_);
    convert_x<<<8192, 256>>>(K, x + (size_t)XK_ROW * DM_);
    convert_x<<<8192, 256>>>(V, x + (size_t)XV_ROW * DM_);

    // ---- projections (fp16 single-pass tensor-core) ----
    gemm_h<<<dim3(8, 16), 256, GEMM_SMEM>>>(x + (size_t)XQ_ROW * DM_, wt + 0 * WS, bq, nullptr, LQ_, 0);
    gemm_h<<<dim3(8, 64), 256, GEMM_SMEM>>>(x + (size_t)XK_ROW * DM_, wt + 1 * WS, bk, nullptr, LK_, 1);
    gemm_h<<<dim3(8, 64), 256, GEMM_SMEM>>>(x + (size_t)XV_ROW * DM_, wt + 2 * WS, bv, nullptr, LK_, 2);

    // ---- attention ----
    flash_attn<<<dim3(LQ_ / 64, H_, B_), 128, FA_SMEM>>>(mask);

    // ---- output projection + residual ----
    gemm_h<<<dim3(8, 16), 256, GEMM_SMEM>>>((const __half*)ao, wt + 3 * WS, bo, Q, LQ_, 3);

    // ---- layernorm ----
    layernorm_kernel<<<B_ * LQ_, 256>>>(gamma, beta, out);
}

// round 10
// speedup vs baseline: 2.1890x; 1.1057x over previous
#include <cuda_runtime.h>
#include <cuda_fp16.h>
#include <math.h>
#include <stdint.h>

#define B_  4
#define H_  16
#define LQ_ 512
#define LK_ 2048
#define DM_ 1024

#define XQ_ROW 0
#define XK_ROW 2048
#define XV_ROW (2048 + 8192)

// ---------------------------------------------------------------------------
// Scratch (device globals; no runtime allocation allowed)
// ---------------------------------------------------------------------------
__device__ __align__(16) __half    g_wt [(size_t)4 * DM_ * DM_];     // W^T [mat][n][k] fp16
__device__ __align__(16) __half    g_x  [(size_t)18432 * DM_];       // X fp16 [row][k]
__device__ __align__(16) uint32_t  g_q  [(size_t)B_*H_*LQ_*32];      // q [b,h,l,dpair] half2
__device__ __align__(16) uint32_t  g_k  [(size_t)B_*H_*LK_*32];      // k [b,h,l,dpair] half2
__device__ __align__(16) __half    g_vt [(size_t)B_*H_*64*LK_];      // V^T [b,h,d,key] fp16
__device__ __align__(16) uint32_t  g_ao [(size_t)B_*LQ_*512];        // attn out [row][dpair] half2
__device__ __align__(16) float     g_y  [(size_t)B_*LQ_*DM_];        // pre-LN

// ---------------------------------------------------------------------------
// helpers
// ---------------------------------------------------------------------------
__device__ __forceinline__ uint32_t packh(float e, float o) {
    uint32_t r;
    asm("cvt.rn.f16x2.f32 %0, %1, %2;" : "=r"(r) : "f"(o), "f"(e));
    return r;
}

__device__ __forceinline__ void mma_f16(float c[4],
                                        uint32_t a0, uint32_t a1, uint32_t a2, uint32_t a3,
                                        uint32_t b0, uint32_t b1)
{
    asm volatile(
        "mma.sync.aligned.m16n8k16.row.col.f32.f16.f16.f32 "
        "{%0,%1,%2,%3}, {%4,%5,%6,%7}, {%8,%9}, {%0,%1,%2,%3};"
        : "+f"(c[0]), "+f"(c[1]), "+f"(c[2]), "+f"(c[3])
        : "r"(a0), "r"(a1), "r"(a2), "r"(a3), "r"(b0), "r"(b1));
}

// ---------------------------------------------------------------------------
// Pre-pass: all X fp32 -> fp16, one launch. Block = one 1024-wide row.
// ---------------------------------------------------------------------------
__global__ void convert_x_all(const float* __restrict__ Q, const float* __restrict__ K,
                              const float* __restrict__ V, __half* __restrict__ dst)
{
    const int row = blockIdx.x;
    const float* src;
    int lr;
    if (row < 2048)       { src = Q; lr = row; }
    else if (row < 10240) { src = K; lr = row - 2048; }
    else                  { src = V; lr = row - 10240; }
    float4 v = ((const float4*)(src + (size_t)lr * DM_))[threadIdx.x];
    uint2 p;
    p.x = packh(v.x, v.y);
    p.y = packh(v.z, v.w);
    ((uint2*)(dst + (size_t)row * DM_))[threadIdx.x] = p;
}

// Pre-pass: all W [k][n] fp32 -> W^T [n][k] fp16, one launch (z = matrix)
__global__ void convert_wt_all(const float* __restrict__ W0, const float* __restrict__ W1,
                               const float* __restrict__ W2, const float* __restrict__ W3,
                               __half* __restrict__ T)
{
    __shared__ float tile[64][65];
    const int z = blockIdx.z;
    const float* W = (z == 0) ? W0 : (z == 1) ? W1 : (z == 2) ? W2 : W3;
    __half* Tz = T + (size_t)z * DM_ * DM_;
    const int n0 = blockIdx.x * 64, k0 = blockIdx.y * 64;
    const int tid = threadIdx.x;
    #pragma unroll
    for (int i = 0; i < 16; i++) {
        int idx = tid + i * 256;
        int r = idx >> 6, c = idx & 63;
        tile[r][c] = W[(size_t)(k0 + r) * DM_ + n0 + c];
    }
    __syncthreads();
    #pragma unroll
    for (int i = 0; i < 16; i++) {
        int idx = tid + i * 256;
        int nr = idx >> 6, kc = idx & 63;
        Tz[(size_t)(n0 + nr) * DM_ + k0 + kc] = __float2half(tile[kc][nr]);
    }
}

// ---------------------------------------------------------------------------
// fp16 single-pass GEMM with register-prefetch double buffering.
// CTA 128x128, BK=32 (16 kpairs), 256 thr (8 warps 2x4), warp tile 64x32.
// outMode: 0 -> g_q, 1 -> g_k, 2 -> g_vt (V^T), 3 -> g_y (+resid)
// ---------------------------------------------------------------------------
#define GS_A 0
#define GS_B (128 * 20)
#define GEMM_SMEM (2 * 128 * 20 * 4)

__global__ __launch_bounds__(256, 2)
void gemm_h(const __half* __restrict__ A_g, const __half* __restrict__ B_g,
            const float* __restrict__ bias, const float* __restrict__ resid,
            int L, int outMode)
{
    extern __shared__ uint32_t sm[];
    uint32_t* As = sm + GS_A;
    uint32_t* Bs = sm + GS_B;

    const uint32_t* a32 = (const uint32_t*)A_g;
    const uint32_t* b32 = (const uint32_t*)B_g;

    const int row0 = blockIdx.y * 128;
    const int col0 = blockIdx.x * 128;
    const int tid  = threadIdx.x;
    const int lane = tid & 31;
    const int w    = tid >> 5;
    const int wm   = (w >> 2) * 64;
    const int wn   = (w & 3) * 32;
    const int grp  = lane >> 2;
    const int tg   = lane & 3;

    float acc[4][4][4] = {};

    const int fm = tid >> 1;            // 0..127 (row)
    const int fo = (tid & 1) * 8;       // u32 offset {0,8}; covers 8 contiguous u32 x2

    uint4 pA0, pA1, pB0, pB1;
    auto gload = [&](int kp0) {
        const size_t ga = (size_t)(row0 + fm) * 512 + kp0 + fo;
        const size_t gb = (size_t)(col0 + fm) * 512 + kp0 + fo;
        pA0 = *(const uint4*)&a32[ga];
        pA1 = *(const uint4*)&a32[ga + 4];
        pB0 = *(const uint4*)&b32[gb];
        pB1 = *(const uint4*)&b32[gb + 4];
    };
    auto sts = [&]() {
        *(uint4*)&As[fm * 20 + fo]     = pA0;
        *(uint4*)&As[fm * 20 + fo + 4] = pA1;
        *(uint4*)&Bs[fm * 20 + fo]     = pB0;
        *(uint4*)&Bs[fm * 20 + fo + 4] = pB1;
    };

    gload(0);
    sts();
    __syncthreads();

    for (int t = 0; t < 32; t++) {
        if (t < 31) gload((t + 1) * 16);

        #pragma unroll
        for (int kt = 0; kt < 2; kt++) {
            const int kb = kt * 8;
            uint32_t bf[4][2];
            #pragma unroll
            for (int nt = 0; nt < 4; nt++) {
                int cc = wn + nt * 8 + grp;
                bf[nt][0] = Bs[cc * 20 + kb + tg];
                bf[nt][1] = Bs[cc * 20 + kb + tg + 4];
            }
            #pragma unroll
            for (int m = 0; m < 4; m++) {
                int r = wm + m * 16 + grp;
                uint32_t a0 = As[r * 20 + kb + tg];
                uint32_t a1 = As[(r + 8) * 20 + kb + tg];
                uint32_t a2 = As[r * 20 + kb + tg + 4];
                uint32_t a3 = As[(r + 8) * 20 + kb + tg + 4];
                #pragma unroll
                for (int nt = 0; nt < 4; nt++)
                    mma_f16(acc[m][nt], a0, a1, a2, a3, bf[nt][0], bf[nt][1]);
            }
        }

        if (t < 31) {
            __syncthreads();
            sts();
            __syncthreads();
        }
    }

    // ---- epilogue ----
    #pragma unroll
    for (int nt = 0; nt < 4; nt++) {
        const int gc = col0 + wn + nt * 8 + tg * 2;
        const float b0 = bias[gc], b1 = bias[gc + 1];
        #pragma unroll
        for (int m = 0; m < 4; m++) {
            int r0 = row0 + wm + m * 16 + grp;
            int r1 = r0 + 8;
            float v00 = acc[m][nt][0] + b0, v01 = acc[m][nt][1] + b1;
            float v10 = acc[m][nt][2] + b0, v11 = acc[m][nt][3] + b1;
            if (outMode == 3) {
                float2 rr0 = *(const float2*)&resid[(size_t)r0 * DM_ + gc];
                float2 rr1 = *(const float2*)&resid[(size_t)r1 * DM_ + gc];
                float2 o0 = {v00 + rr0.x, v01 + rr0.y};
                float2 o1 = {v10 + rr1.x, v11 + rr1.y};
                *(float2*)&g_y[(size_t)r0 * DM_ + gc] = o0;
                *(float2*)&g_y[(size_t)r1 * DM_ + gc] = o1;
            } else if (outMode == 2) {
                const int hh = gc >> 6, d = gc & 63;
                const int b0i = r0 / L, k0i = r0 % L;
                const int b1i = r1 / L, k1i = r1 % L;
                size_t base0 = (size_t)(b0i * H_ + hh) * 64;
                size_t base1 = (size_t)(b1i * H_ + hh) * 64;
                g_vt[(base0 + d)     * LK_ + k0i] = __float2half(v00);
                g_vt[(base0 + d + 1) * LK_ + k0i] = __float2half(v01);
                g_vt[(base1 + d)     * LK_ + k1i] = __float2half(v10);
                g_vt[(base1 + d + 1) * LK_ + k1i] = __float2half(v11);
            } else {
                const int hh = gc >> 6, dp = (gc & 63) >> 1;
                const int b0i = r0 / L, ll0 = r0 % L;
                const int b1i = r1 / L, ll1 = r1 % L;
                uint32_t* oq = (outMode == 0) ? g_q : g_k;
                oq[((size_t)(b0i * H_ + hh) * L + ll0) * 32 + dp] = packh(v00, v01);
                oq[((size_t)(b1i * H_ + hh) * L + ll1) * 32 + dp] = packh(v10, v11);
            }
        }
    }
}

// ---------------------------------------------------------------------------
// fp16 flash attention with register-prefetched K/V tiles.
// Block (64q, h, b), 128 thr (4 warps, warp = 16 q rows).
// Smem rows are 32 u32 (36 stride); 2 threads/row -> each thread covers
// 16 u32 = 4 uint4 at offsets fh + {0,4,8,12}, fh in {0,16}.
// ---------------------------------------------------------------------------
#define FS_Q 0
#define FS_K (64 * 36)
#define FS_V (2 * 64 * 36)
#define FS_MSK (3 * 64 * 36)
#define FA_SMEM ((FS_MSK + 64) * 4)

__global__ __launch_bounds__(128)
void flash_attn(const int* __restrict__ mask)
{
    extern __shared__ uint32_t sm[];
    uint32_t* Qs = sm + FS_Q;
    uint32_t* Ks = sm + FS_K;
    uint32_t* Vs = sm + FS_V;
    float*   msk = (float*)(sm + FS_MSK);

    const int q0 = blockIdx.x * 64, h = blockIdx.y, b = blockIdx.z;
    const int tid  = threadIdx.x;
    const int lane = tid & 31;
    const int w    = tid >> 5;
    const int grp  = lane >> 2;
    const int tg   = lane & 3;

    const size_t bh_off = (size_t)(b * H_ + h);
    const uint32_t* kq_g = g_k + bh_off * LK_ * 32;
    const uint32_t* vt32 = (const uint32_t*)(g_vt + bh_off * 64 * LK_);
    const int* mk_g = mask + b * LK_;

    const int fr = tid >> 1, fh = (tid & 1) * 16;

    uint4 pk[4], pv[4];
    int pm;
    auto gload = [&](int k0) {
        #pragma unroll
        for (int i = 0; i < 4; i++) {
            pk[i] = *(const uint4*)&kq_g[(size_t)(k0 + fr) * 32 + fh + i * 4];
            pv[i] = *(const uint4*)&vt32[(size_t)fr * (LK_ / 2) + (k0 >> 1) + fh + i * 4];
        }
        pm = (tid < 64) ? mk_g[k0 + tid] : 0;
    };
    auto sts = [&]() {
        #pragma unroll
        for (int i = 0; i < 4; i++) {
            *(uint4*)&Ks[fr * 36 + fh + i * 4] = pk[i];
            *(uint4*)&Vs[fr * 36 + fh + i * 4] = pv[i];
        }
        if (tid < 64) msk[tid] = (pm == 0) ? -1e30f : 0.0f;
    };

    // ---- load Q tile + stage 0 ----
    {
        const uint32_t* qg = g_q + (bh_off * LQ_ + q0) * 32;
        #pragma unroll
        for (int i = 0; i < 4; i++)
            *(uint4*)&Qs[fr * 36 + fh + i * 4] = *(const uint4*)&qg[(size_t)fr * 32 + fh + i * 4];
    }
    gload(0);
    sts();
    __syncthreads();

    // ---- Q fragments (registers for whole mainloop) ----
    uint32_t qf[4][4];
    {
        const int r = w * 16 + grp;
        #pragma unroll
        for (int kt = 0; kt < 4; kt++) {
            const int kb = kt * 8;
            qf[kt][0] = Qs[r * 36 + kb + tg];
            qf[kt][1] = Qs[(r + 8) * 36 + kb + tg];
            qf[kt][2] = Qs[r * 36 + kb + tg + 4];
            qf[kt][3] = Qs[(r + 8) * 36 + kb + tg + 4];
        }
    }

    float oacc[8][4];
    #pragma unroll
    for (int nt = 0; nt < 8; nt++)
        #pragma unroll
        for (int j = 0; j < 4; j++) oacc[nt][j] = 0.f;
    float m0 = -1e30f, m1 = -1e30f, lsum0 = 0.f, lsum1 = 0.f;

    const int NT = LK_ / 64;
    for (int t = 0; t < NT; t++) {
        if (t + 1 < NT) gload((t + 1) * 64);

        // ---- S = Q K^T ----
        float s[8][4];
        #pragma unroll
        for (int nt = 0; nt < 8; nt++)
            #pragma unroll
            for (int j = 0; j < 4; j++) s[nt][j] = 0.f;

        #pragma unroll
        for (int kt = 0; kt < 4; kt++) {
            const int kb = kt * 8;
            #pragma unroll
            for (int nt = 0; nt < 8; nt++) {
                int cc = nt * 8 + grp;
                uint32_t b0 = Ks[cc * 36 + kb + tg];
                uint32_t b1 = Ks[cc * 36 + kb + tg + 4];
                mma_f16(s[nt], qf[kt][0], qf[kt][1], qf[kt][2], qf[kt][3], b0, b1);
            }
        }

        // ---- online softmax ----
        const float scl = 0.125f;
        float rmax0 = -1e30f, rmax1 = -1e30f;
        #pragma unroll
        for (int nt = 0; nt < 8; nt++) {
            float mk0 = msk[nt * 8 + 2 * tg];
            float mk1 = msk[nt * 8 + 2 * tg + 1];
            s[nt][0] = s[nt][0] * scl + mk0;
            s[nt][1] = s[nt][1] * scl + mk1;
            s[nt][2] = s[nt][2] * scl + mk0;
            s[nt][3] = s[nt][3] * scl + mk1;
            rmax0 = fmaxf(rmax0, fmaxf(s[nt][0], s[nt][1]));
            rmax1 = fmaxf(rmax1, fmaxf(s[nt][2], s[nt][3]));
        }
        rmax0 = fmaxf(rmax0, __shfl_xor_sync(0xffffffffu, rmax0, 1));
        rmax0 = fmaxf(rmax0, __shfl_xor_sync(0xffffffffu, rmax0, 2));
        rmax1 = fmaxf(rmax1, __shfl_xor_sync(0xffffffffu, rmax1, 1));
        rmax1 = fmaxf(rmax1, __shfl_xor_sync(0xffffffffu, rmax1, 2));

        float mn0 = fmaxf(m0, rmax0), mn1 = fmaxf(m1, rmax1);
        float c0 = __expf(m0 - mn0),  c1 = __expf(m1 - mn1);
        m0 = mn0; m1 = mn1;

        float sum0 = 0.f, sum1 = 0.f;
        #pragma unroll
        for (int nt = 0; nt < 8; nt++) {
            s[nt][0] = __expf(s[nt][0] - mn0);
            s[nt][1] = __expf(s[nt][1] - mn0);
            s[nt][2] = __expf(s[nt][2] - mn1);
            s[nt][3] = __expf(s[nt][3] - mn1);
            sum0 += s[nt][0] + s[nt][1];
            sum1 += s[nt][2] + s[nt][3];
        }
        sum0 += __shfl_xor_sync(0xffffffffu, sum0, 1);
        sum0 += __shfl_xor_sync(0xffffffffu, sum0, 2);
        sum1 += __shfl_xor_sync(0xffffffffu, sum1, 1);
        sum1 += __shfl_xor_sync(0xffffffffu, sum1, 2);
        lsum0 = lsum0 * c0 + sum0;
        lsum1 = lsum1 * c1 + sum1;

        #pragma unroll
        for (int nt = 0; nt < 8; nt++) {
            oacc[nt][0] *= c0; oacc[nt][1] *= c0;
            oacc[nt][2] *= c1; oacc[nt][3] *= c1;
        }

        // ---- O += P V ----
        #pragma unroll
        for (int kg = 0; kg < 4; kg++) {
            uint32_t pa0 = packh(s[2*kg][0],   s[2*kg][1]);
            uint32_t pa1 = packh(s[2*kg][2],   s[2*kg][3]);
            uint32_t pa2 = packh(s[2*kg+1][0], s[2*kg+1][1]);
            uint32_t pa3 = packh(s[2*kg+1][2], s[2*kg+1][3]);
            const int kb = kg * 8;
            #pragma unroll
            for (int nt = 0; nt < 8; nt++) {
                int cc = nt * 8 + grp;
                uint32_t b0 = Vs[cc * 36 + kb + tg];
                uint32_t b1 = Vs[cc * 36 + kb + tg + 4];
                mma_f16(oacc[nt], pa0, pa1, pa2, pa3, b0, b1);
            }
        }

        if (t + 1 < NT) {
            __syncthreads();
            sts();
            __syncthreads();
        }
    }

    // ---- epilogue: packed fp16 attention output ----
    float inv0 = 1.0f / lsum0, inv1 = 1.0f / lsum1;
    int qr0 = q0 + w * 16 + grp;
    int qr1 = qr0 + 8;
    size_t r0base = ((size_t)b * LQ_ + qr0) * 512 + h * 32;
    size_t r1base = ((size_t)b * LQ_ + qr1) * 512 + h * 32;
    #pragma unroll
    for (int nt = 0; nt < 8; nt++) {
        int dp = nt * 4 + tg;
        g_ao[r0base + dp] = packh(oacc[nt][0] * inv0, oacc[nt][1] * inv0);
        g_ao[r1base + dp] = packh(oacc[nt][2] * inv1, oacc[nt][3] * inv1);
    }
}

// ---------------------------------------------------------------------------
// LayerNorm per row of g_y
// ---------------------------------------------------------------------------
__global__ void layernorm_kernel(const float* __restrict__ gamma,
                                 const float* __restrict__ beta,
                                 float* __restrict__ out)
{
    const int row = blockIdx.x;
    const int tid = threadIdx.x;
    __shared__ float red[256];

    const float* yr = g_y + (size_t)row * DM_;
    float4 xv = *(const float4*)(yr + tid * 4);

    float s = xv.x + xv.y + xv.z + xv.w;
    red[tid] = s; __syncthreads();
    #pragma unroll
    for (int st = 128; st > 0; st >>= 1) {
        if (tid < st) red[tid] += red[tid + st];
        __syncthreads();
    }
    float mean = red[0] * (1.0f / DM_);
    __syncthreads();

    float dx = xv.x - mean, dy = xv.y - mean, dz = xv.z - mean, dw = xv.w - mean;
    float sq = dx * dx + dy * dy + dz * dz + dw * dw;
    red[tid] = sq; __syncthreads();
    #pragma unroll
    for (int st = 128; st > 0; st >>= 1) {
        if (tid < st) red[tid] += red[tid + st];
        __syncthreads();
    }
    float rstd = rsqrtf(red[0] * (1.0f / DM_) + 1e-5f);

    int n = tid * 4;
    float4 ov;
    ov.x = dx * rstd * gamma[n]     + beta[n];
    ov.y = dy * rstd * gamma[n + 1] + beta[n + 1];
    ov.z = dz * rstd * gamma[n + 2] + beta[n + 2];
    ov.w = dw * rstd * gamma[n + 3] + beta[n + 3];
    *(float4*)(out + (size_t)row * DM_ + n) = ov;
}

// ---------------------------------------------------------------------------
extern "C" void kernel_launch(void* const* d_in, const int* in_sizes, int n_in,
                              void* d_out, int out_size)
{
    const float* Q    = (const float*)d_in[0];
    const float* K    = (const float*)d_in[1];
    const float* V    = (const float*)d_in[2];
    /* d_in[3] = node_num (unused) */
    const int*   mask = (const int*)  d_in[4];
    const float* Wq   = (const float*)d_in[5];
    const float* bq   = (const float*)d_in[6];
    const float* Wk   = (const float*)d_in[7];
    const float* bk   = (const float*)d_in[8];
    const float* Wv   = (const float*)d_in[9];
    const float* bv   = (const float*)d_in[10];
    const float* Wo   = (const float*)d_in[11];
    const float* bo   = (const float*)d_in[12];
    const float* gamma= (const float*)d_in[13];
    const float* beta = (const float*)d_in[14];
    float* out = (float*)d_out;

    cudaFuncSetAttribute(gemm_h,     cudaFuncAttributeMaxDynamicSharedMemorySize, GEMM_SMEM);
    cudaFuncSetAttribute(flash_attn, cudaFuncAttributeMaxDynamicSharedMemorySize, FA_SMEM);

    __half *wt, *x;
    uint32_t *ao;
    cudaGetSymbolAddress((void**)&wt, g_wt);
    cudaGetSymbolAddress((void**)&x,  g_x);
    cudaGetSymbolAddress((void**)&ao, g_ao);

    const size_t WS = (size_t)DM_ * DM_;

    // ---- pre-pass conversions (2 launches) ----
    convert_wt_all<<<dim3(16, 16, 4), 256>>>(Wq, Wk, Wv, Wo, wt);
    convert_x_all<<<18432, 256>>>(Q, K, V, x);

    // ---- projections (fp16 single-pass tensor-core) ----
    gemm_h<<<dim3(8, 16), 256, GEMM_SMEM>>>(x + (size_t)XQ_ROW * DM_, wt + 0 * WS, bq, nullptr, LQ_, 0);
    gemm_h<<<dim3(8, 64), 256, GEMM_SMEM>>>(x + (size_t)XK_ROW * DM_, wt + 1 * WS, bk, nullptr, LK_, 1);
    gemm_h<<<dim3(8, 64), 256, GEMM_SMEM>>>(x + (size_t)XV_ROW * DM_, wt + 2 * WS, bv, nullptr, LK_, 2);

    // ---- attention ----
    flash_attn<<<dim3(LQ_ / 64, H_, B_), 128, FA_SMEM>>>(mask);

    // ---- output projection + residual ----
    gemm_h<<<dim3(8, 16), 256, GEMM_SMEM>>>((const __half*)ao, wt + 3 * WS, bo, Q, LQ_, 3);

    // ---- layernorm ----
    layernorm_kernel<<<B_ * LQ_, 256>>>(gamma, beta, out);
}

// round 11
// speedup vs baseline: 2.2378x; 1.0223x over previous
#include <cuda_runtime.h>
#include <cuda_fp16.h>
#include <math.h>
#include <stdint.h>

#define B_  4
#define H_  16
#define LQ_ 512
#define LK_ 2048
#define DM_ 1024

#define XQ_ROW 0
#define XK_ROW 2048
#define XV_ROW (2048 + 8192)

// ---------------------------------------------------------------------------
// Scratch (device globals; no runtime allocation allowed)
// ---------------------------------------------------------------------------
__device__ __align__(16) __half    g_wt [(size_t)4 * DM_ * DM_];     // W^T [mat][n][k] fp16
__device__ __align__(16) __half    g_x  [(size_t)18432 * DM_];       // X fp16 [row][k]
__device__ __align__(16) uint32_t  g_q  [(size_t)B_*H_*LQ_*32];      // q [b,h,l,dpair] half2
__device__ __align__(16) uint32_t  g_k  [(size_t)B_*H_*LK_*32];      // k [b,h,l,dpair] half2
__device__ __align__(16) __half    g_vt [(size_t)B_*H_*64*LK_];      // V^T [b,h,d,key] fp16
__device__ __align__(16) uint32_t  g_ao [(size_t)B_*LQ_*512];        // attn out [row][dpair] half2
__device__ __align__(16) float     g_y  [(size_t)B_*LQ_*DM_];        // pre-LN

// ---------------------------------------------------------------------------
// helpers
// ---------------------------------------------------------------------------
__device__ __forceinline__ uint32_t packh(float e, float o) {
    uint32_t r;
    asm("cvt.rn.f16x2.f32 %0, %1, %2;" : "=r"(r) : "f"(o), "f"(e));
    return r;
}

__device__ __forceinline__ void mma_f16(float c[4],
                                        uint32_t a0, uint32_t a1, uint32_t a2, uint32_t a3,
                                        uint32_t b0, uint32_t b1)
{
    asm volatile(
        "mma.sync.aligned.m16n8k16.row.col.f32.f16.f16.f32 "
        "{%0,%1,%2,%3}, {%4,%5,%6,%7}, {%8,%9}, {%0,%1,%2,%3};"
        : "+f"(c[0]), "+f"(c[1]), "+f"(c[2]), "+f"(c[3])
        : "r"(a0), "r"(a1), "r"(a2), "r"(a3), "r"(b0), "r"(b1));
}

__device__ __forceinline__ void ldsm4(uint32_t& r0, uint32_t& r1, uint32_t& r2, uint32_t& r3,
                                      uint32_t addr)
{
    asm volatile("ldmatrix.sync.aligned.m8n8.x4.shared.b16 {%0,%1,%2,%3}, [%4];"
                 : "=r"(r0), "=r"(r1), "=r"(r2), "=r"(r3) : "r"(addr));
}

__device__ __forceinline__ uint32_t smem_u32(const void* p) {
    uint32_t a;
    asm("{ .reg .u64 t; cvta.to.shared.u64 t, %1; cvt.u32.u64 %0, t; }" : "=r"(a) : "l"(p));
    return a;
}

// ---------------------------------------------------------------------------
// Pre-pass: all X fp32 -> fp16, one launch. Block = one 1024-wide row.
// ---------------------------------------------------------------------------
__global__ void convert_x_all(const float* __restrict__ Q, const float* __restrict__ K,
                              const float* __restrict__ V, __half* __restrict__ dst)
{
    const int row = blockIdx.x;
    const float* src;
    int lr;
    if (row < 2048)       { src = Q; lr = row; }
    else if (row < 10240) { src = K; lr = row - 2048; }
    else                  { src = V; lr = row - 10240; }
    float4 v = ((const float4*)(src + (size_t)lr * DM_))[threadIdx.x];
    uint2 p;
    p.x = packh(v.x, v.y);
    p.y = packh(v.z, v.w);
    ((uint2*)(dst + (size_t)row * DM_))[threadIdx.x] = p;
}

// Pre-pass: all W [k][n] fp32 -> W^T [n][k] fp16, one launch (z = matrix)
__global__ void convert_wt_all(const float* __restrict__ W0, const float* __restrict__ W1,
                               const float* __restrict__ W2, const float* __restrict__ W3,
                               __half* __restrict__ T)
{
    __shared__ float tile[64][65];
    const int z = blockIdx.z;
    const float* W = (z == 0) ? W0 : (z == 1) ? W1 : (z == 2) ? W2 : W3;
    __half* Tz = T + (size_t)z * DM_ * DM_;
    const int n0 = blockIdx.x * 64, k0 = blockIdx.y * 64;
    const int tid = threadIdx.x;
    #pragma unroll
    for (int i = 0; i < 16; i++) {
        int idx = tid + i * 256;
        int r = idx >> 6, c = idx & 63;
        tile[r][c] = W[(size_t)(k0 + r) * DM_ + n0 + c];
    }
    __syncthreads();
    #pragma unroll
    for (int i = 0; i < 16; i++) {
        int idx = tid + i * 256;
        int nr = idx >> 6, kc = idx & 63;
        Tz[(size_t)(n0 + nr) * DM_ + k0 + kc] = __float2half(tile[kc][nr]);
    }
}

// ---------------------------------------------------------------------------
// fp16 GEMM: register-prefetch double buffering + ldmatrix fragment loads.
// CTA 128x128, BK=32 (16 kpairs), 256 thr (8 warps 2x4), warp tile 64x32.
// Smem layout identical to R10: [row][16 kpairs] stride 20 u32.
// outMode: 0 -> g_q, 1 -> g_k, 2 -> g_vt (V^T), 3 -> g_y (+resid)
// ---------------------------------------------------------------------------
#define GS_A 0
#define GS_B (128 * 20)
#define GEMM_SMEM (2 * 128 * 20 * 4)

__global__ __launch_bounds__(256, 2)
void gemm_h(const __half* __restrict__ A_g, const __half* __restrict__ B_g,
            const float* __restrict__ bias, const float* __restrict__ resid,
            int L, int outMode)
{
    extern __shared__ uint32_t sm[];
    uint32_t* As = sm + GS_A;
    uint32_t* Bs = sm + GS_B;

    const uint32_t* a32 = (const uint32_t*)A_g;
    const uint32_t* b32 = (const uint32_t*)B_g;

    const int row0 = blockIdx.y * 128;
    const int col0 = blockIdx.x * 128;
    const int tid  = threadIdx.x;
    const int lane = tid & 31;
    const int w    = tid >> 5;
    const int wm   = (w >> 2) * 64;
    const int wn   = (w & 3) * 32;
    const int grp  = lane >> 2;
    const int tg   = lane & 3;

    // ldmatrix per-lane row-address offsets (u32 units), loop-invariant.
    // A (mats: (r,kb),(r+8,kb),(r,kb+4),(r+8,kb+4)):
    const int aoff = (((lane >> 3) & 1) * 8 + (lane & 7)) * 20 + (lane >> 4) * 4;
    // B (mats: (nt0,kb),(nt0,kb+4),(nt1,kb),(nt1,kb+4)):
    const int boff = ((lane >> 4) * 8 + (lane & 7)) * 20 + ((lane >> 3) & 1) * 4;

    const uint32_t sA = smem_u32(As) + 4 * aoff;
    const uint32_t sB = smem_u32(Bs) + 4 * boff;

    float acc[4][4][4] = {};

    const int fm = tid >> 1;            // 0..127 (row)
    const int fo = (tid & 1) * 8;       // u32 offset {0,8}

    uint4 pA0, pA1, pB0, pB1;
    auto gload = [&](int kp0) {
        const size_t ga = (size_t)(row0 + fm) * 512 + kp0 + fo;
        const size_t gb = (size_t)(col0 + fm) * 512 + kp0 + fo;
        pA0 = *(const uint4*)&a32[ga];
        pA1 = *(const uint4*)&a32[ga + 4];
        pB0 = *(const uint4*)&b32[gb];
        pB1 = *(const uint4*)&b32[gb + 4];
    };
    auto sts = [&]() {
        *(uint4*)&As[fm * 20 + fo]     = pA0;
        *(uint4*)&As[fm * 20 + fo + 4] = pA1;
        *(uint4*)&Bs[fm * 20 + fo]     = pB0;
        *(uint4*)&Bs[fm * 20 + fo + 4] = pB1;
    };

    gload(0);
    sts();
    __syncthreads();

    for (int t = 0; t < 32; t++) {
        if (t < 31) gload((t + 1) * 16);

        #pragma unroll
        for (int kt = 0; kt < 2; kt++) {
            const int kb = kt * 8;
            uint32_t bf[4][2];
            #pragma unroll
            for (int np = 0; np < 2; np++) {
                uint32_t addrB = sB + 4 * ((wn + np * 16) * 20 + kb);
                ldsm4(bf[2*np][0], bf[2*np][1], bf[2*np+1][0], bf[2*np+1][1], addrB);
            }
            #pragma unroll
            for (int m = 0; m < 4; m++) {
                uint32_t addrA = sA + 4 * ((wm + m * 16) * 20 + kb);
                uint32_t a0, a1, a2, a3;
                ldsm4(a0, a1, a2, a3, addrA);
                #pragma unroll
                for (int nt = 0; nt < 4; nt++)
                    mma_f16(acc[m][nt], a0, a1, a2, a3, bf[nt][0], bf[nt][1]);
            }
        }

        if (t < 31) {
            __syncthreads();
            sts();
            __syncthreads();
        }
    }

    // ---- epilogue ----
    #pragma unroll
    for (int nt = 0; nt < 4; nt++) {
        const int gc = col0 + wn + nt * 8 + tg * 2;
        const float b0 = bias[gc], b1 = bias[gc + 1];
        #pragma unroll
        for (int m = 0; m < 4; m++) {
            int r0 = row0 + wm + m * 16 + grp;
            int r1 = r0 + 8;
            float v00 = acc[m][nt][0] + b0, v01 = acc[m][nt][1] + b1;
            float v10 = acc[m][nt][2] + b0, v11 = acc[m][nt][3] + b1;
            if (outMode == 3) {
                float2 rr0 = *(const float2*)&resid[(size_t)r0 * DM_ + gc];
                float2 rr1 = *(const float2*)&resid[(size_t)r1 * DM_ + gc];
                float2 o0 = {v00 + rr0.x, v01 + rr0.y};
                float2 o1 = {v10 + rr1.x, v11 + rr1.y};
                *(float2*)&g_y[(size_t)r0 * DM_ + gc] = o0;
                *(float2*)&g_y[(size_t)r1 * DM_ + gc] = o1;
            } else if (outMode == 2) {
                const int hh = gc >> 6, d = gc & 63;
                const int b0i = r0 / L, k0i = r0 % L;
                const int b1i = r1 / L, k1i = r1 % L;
                size_t base0 = (size_t)(b0i * H_ + hh) * 64;
                size_t base1 = (size_t)(b1i * H_ + hh) * 64;
                g_vt[(base0 + d)     * LK_ + k0i] = __float2half(v00);
                g_vt[(base0 + d + 1) * LK_ + k0i] = __float2half(v01);
                g_vt[(base1 + d)     * LK_ + k1i] = __float2half(v10);
                g_vt[(base1 + d + 1) * LK_ + k1i] = __float2half(v11);
            } else {
                const int hh = gc >> 6, dp = (gc & 63) >> 1;
                const int b0i = r0 / L, ll0 = r0 % L;
                const int b1i = r1 / L, ll1 = r1 % L;
                uint32_t* oq = (outMode == 0) ? g_q : g_k;
                oq[((size_t)(b0i * H_ + hh) * L + ll0) * 32 + dp] = packh(v00, v01);
                oq[((size_t)(b1i * H_ + hh) * L + ll1) * 32 + dp] = packh(v10, v11);
            }
        }
    }
}

// ---------------------------------------------------------------------------
// fp16 flash attention: register-prefetched K/V tiles + ldmatrix fragments.
// Block (64q, h, b), 128 thr (4 warps, warp = 16 q rows).
// Smem layout identical to R10: rows of 32 u32, stride 36.
// ---------------------------------------------------------------------------
#define FS_Q 0
#define FS_K (64 * 36)
#define FS_V (2 * 64 * 36)
#define FS_MSK (3 * 64 * 36)
#define FA_SMEM ((FS_MSK + 64) * 4)

__global__ __launch_bounds__(128)
void flash_attn(const int* __restrict__ mask)
{
    extern __shared__ uint32_t sm[];
    uint32_t* Qs = sm + FS_Q;
    uint32_t* Ks = sm + FS_K;
    uint32_t* Vs = sm + FS_V;
    float*   msk = (float*)(sm + FS_MSK);

    const int q0 = blockIdx.x * 64, h = blockIdx.y, b = blockIdx.z;
    const int tid  = threadIdx.x;
    const int lane = tid & 31;
    const int w    = tid >> 5;
    const int grp  = lane >> 2;
    const int tg   = lane & 3;

    const size_t bh_off = (size_t)(b * H_ + h);
    const uint32_t* kq_g = g_k + bh_off * LK_ * 32;
    const uint32_t* vt32 = (const uint32_t*)(g_vt + bh_off * 64 * LK_);
    const int* mk_g = mask + b * LK_;

    const int fr = tid >> 1, fh = (tid & 1) * 16;

    // ldmatrix B-type per-lane offsets (stride 36 layout)
    const int koff = ((lane >> 4) * 8 + (lane & 7)) * 36 + ((lane >> 3) & 1) * 4;
    const uint32_t sK = smem_u32(Ks) + 4 * koff;
    const uint32_t sV = smem_u32(Vs) + 4 * koff;

    uint4 pk[4], pv[4];
    int pm;
    auto gload = [&](int k0) {
        #pragma unroll
        for (int i = 0; i < 4; i++) {
            pk[i] = *(const uint4*)&kq_g[(size_t)(k0 + fr) * 32 + fh + i * 4];
            pv[i] = *(const uint4*)&vt32[(size_t)fr * (LK_ / 2) + (k0 >> 1) + fh + i * 4];
        }
        pm = (tid < 64) ? mk_g[k0 + tid] : 0;
    };
    auto sts = [&]() {
        #pragma unroll
        for (int i = 0; i < 4; i++) {
            *(uint4*)&Ks[fr * 36 + fh + i * 4] = pk[i];
            *(uint4*)&Vs[fr * 36 + fh + i * 4] = pv[i];
        }
        if (tid < 64) msk[tid] = (pm == 0) ? -1e30f : 0.0f;
    };

    // ---- load Q tile + stage 0 ----
    {
        const uint32_t* qg = g_q + (bh_off * LQ_ + q0) * 32;
        #pragma unroll
        for (int i = 0; i < 4; i++)
            *(uint4*)&Qs[fr * 36 + fh + i * 4] = *(const uint4*)&qg[(size_t)fr * 32 + fh + i * 4];
    }
    gload(0);
    sts();
    __syncthreads();

    // ---- Q fragments (registers for whole mainloop) ----
    uint32_t qf[4][4];
    {
        const int r = w * 16 + grp;
        #pragma unroll
        for (int kt = 0; kt < 4; kt++) {
            const int kb = kt * 8;
            qf[kt][0] = Qs[r * 36 + kb + tg];
            qf[kt][1] = Qs[(r + 8) * 36 + kb + tg];
            qf[kt][2] = Qs[r * 36 + kb + tg + 4];
            qf[kt][3] = Qs[(r + 8) * 36 + kb + tg + 4];
        }
    }

    float oacc[8][4];
    #pragma unroll
    for (int nt = 0; nt < 8; nt++)
        #pragma unroll
        for (int j = 0; j < 4; j++) oacc[nt][j] = 0.f;
    float m0 = -1e30f, m1 = -1e30f, lsum0 = 0.f, lsum1 = 0.f;

    const int NT = LK_ / 64;
    for (int t = 0; t < NT; t++) {
        if (t + 1 < NT) gload((t + 1) * 64);

        // ---- S = Q K^T ----
        float s[8][4];
        #pragma unroll
        for (int nt = 0; nt < 8; nt++)
            #pragma unroll
            for (int j = 0; j < 4; j++) s[nt][j] = 0.f;

        #pragma unroll
        for (int kt = 0; kt < 4; kt++) {
            const int kb = kt * 8;
            #pragma unroll
            for (int np = 0; np < 4; np++) {
                uint32_t b0, b1, b2, b3;
                ldsm4(b0, b1, b2, b3, sK + 4 * (np * 16 * 36 + kb));
                mma_f16(s[2*np],   qf[kt][0], qf[kt][1], qf[kt][2], qf[kt][3], b0, b1);
                mma_f16(s[2*np+1], qf[kt][0], qf[kt][1], qf[kt][2], qf[kt][3], b2, b3);
            }
        }

        // ---- online softmax ----
        const float scl = 0.125f;
        float rmax0 = -1e30f, rmax1 = -1e30f;
        #pragma unroll
        for (int nt = 0; nt < 8; nt++) {
            float mk0 = msk[nt * 8 + 2 * tg];
            float mk1 = msk[nt * 8 + 2 * tg + 1];
            s[nt][0] = s[nt][0] * scl + mk0;
            s[nt][1] = s[nt][1] * scl + mk1;
            s[nt][2] = s[nt][2] * scl + mk0;
            s[nt][3] = s[nt][3] * scl + mk1;
            rmax0 = fmaxf(rmax0, fmaxf(s[nt][0], s[nt][1]));
            rmax1 = fmaxf(rmax1, fmaxf(s[nt][2], s[nt][3]));
        }
        rmax0 = fmaxf(rmax0, __shfl_xor_sync(0xffffffffu, rmax0, 1));
        rmax0 = fmaxf(rmax0, __shfl_xor_sync(0xffffffffu, rmax0, 2));
        rmax1 = fmaxf(rmax1, __shfl_xor_sync(0xffffffffu, rmax1, 1));
        rmax1 = fmaxf(rmax1, __shfl_xor_sync(0xffffffffu, rmax1, 2));

        float mn0 = fmaxf(m0, rmax0), mn1 = fmaxf(m1, rmax1);
        float c0 = __expf(m0 - mn0),  c1 = __expf(m1 - mn1);
        m0 = mn0; m1 = mn1;

        float sum0 = 0.f, sum1 = 0.f;
        #pragma unroll
        for (int nt = 0; nt < 8; nt++) {
            s[nt][0] = __expf(s[nt][0] - mn0);
            s[nt][1] = __expf(s[nt][1] - mn0);
            s[nt][2] = __expf(s[nt][2] - mn1);
            s[nt][3] = __expf(s[nt][3] - mn1);
            sum0 += s[nt][0] + s[nt][1];
            sum1 += s[nt][2] + s[nt][3];
        }
        sum0 += __shfl_xor_sync(0xffffffffu, sum0, 1);
        sum0 += __shfl_xor_sync(0xffffffffu, sum0, 2);
        sum1 += __shfl_xor_sync(0xffffffffu, sum1, 1);
        sum1 += __shfl_xor_sync(0xffffffffu, sum1, 2);
        lsum0 = lsum0 * c0 + sum0;
        lsum1 = lsum1 * c1 + sum1;

        #pragma unroll
        for (int nt = 0; nt < 8; nt++) {
            oacc[nt][0] *= c0; oacc[nt][1] *= c0;
            oacc[nt][2] *= c1; oacc[nt][3] *= c1;
        }

        // ---- O += P V ----
        #pragma unroll
        for (int kg = 0; kg < 4; kg++) {
            uint32_t pa0 = packh(s[2*kg][0],   s[2*kg][1]);
            uint32_t pa1 = packh(s[2*kg][2],   s[2*kg][3]);
            uint32_t pa2 = packh(s[2*kg+1][0], s[2*kg+1][1]);
            uint32_t pa3 = packh(s[2*kg+1][2], s[2*kg+1][3]);
            const int kb = kg * 8;
            #pragma unroll
            for (int np = 0; np < 4; np++) {
                uint32_t b0, b1, b2, b3;
                ldsm4(b0, b1, b2, b3, sV + 4 * (np * 16 * 36 + kb));
                mma_f16(oacc[2*np],   pa0, pa1, pa2, pa3, b0, b1);
                mma_f16(oacc[2*np+1], pa0, pa1, pa2, pa3, b2, b3);
            }
        }

        if (t + 1 < NT) {
            __syncthreads();
            sts();
            __syncthreads();
        }
    }

    // ---- epilogue: packed fp16 attention output ----
    float inv0 = 1.0f / lsum0, inv1 = 1.0f / lsum1;
    int qr0 = q0 + w * 16 + grp;
    int qr1 = qr0 + 8;
    size_t r0base = ((size_t)b * LQ_ + qr0) * 512 + h * 32;
    size_t r1base = ((size_t)b * LQ_ + qr1) * 512 + h * 32;
    #pragma unroll
    for (int nt = 0; nt < 8; nt++) {
        int dp = nt * 4 + tg;
        g_ao[r0base + dp] = packh(oacc[nt][0] * inv0, oacc[nt][1] * inv0);
        g_ao[r1base + dp] = packh(oacc[nt][2] * inv1, oacc[nt][3] * inv1);
    }
}

// ---------------------------------------------------------------------------
// LayerNorm per row of g_y
// ---------------------------------------------------------------------------
__global__ void layernorm_kernel(const float* __restrict__ gamma,
                                 const float* __restrict__ beta,
                                 float* __restrict__ out)
{
    const int row = blockIdx.x;
    const int tid = threadIdx.x;
    __shared__ float red[256];

    const float* yr = g_y + (size_t)row * DM_;
    float4 xv = *(const float4*)(yr + tid * 4);

    float s = xv.x + xv.y + xv.z + xv.w;
    red[tid] = s; __syncthreads();
    #pragma unroll
    for (int st = 128; st > 0; st >>= 1) {
        if (tid < st) red[tid] += red[tid + st];
        __syncthreads();
    }
    float mean = red[0] * (1.0f / DM_);
    __syncthreads();

    float dx = xv.x - mean, dy = xv.y - mean, dz = xv.z - mean, dw = xv.w - mean;
    float sq = dx * dx + dy * dy + dz * dz + dw * dw;
    red[tid] = sq; __syncthreads();
    #pragma unroll
    for (int st = 128; st > 0; st >>= 1) {
        if (tid < st) red[tid] += red[tid + st];
        __syncthreads();
    }
    float rstd = rsqrtf(red[0] * (1.0f / DM_) + 1e-5f);

    int n = tid * 4;
    float4 ov;
    ov.x = dx * rstd * gamma[n]     + beta[n];
    ov.y = dy * rstd * gamma[n + 1] + beta[n + 1];
    ov.z = dz * rstd * gamma[n + 2] + beta[n + 2];
    ov.w = dw * rstd * gamma[n + 3] + beta[n + 3];
    *(float4*)(out + (size_t)row * DM_ + n) = ov;
}

// ---------------------------------------------------------------------------
extern "C" void kernel_launch(void* const* d_in, const int* in_sizes, int n_in,
                              void* d_out, int out_size)
{
    const float* Q    = (const float*)d_in[0];
    const float* K    = (const float*)d_in[1];
    const float* V    = (const float*)d_in[2];
    /* d_in[3] = node_num (unused) */
    const int*   mask = (const int*)  d_in[4];
    const float* Wq   = (const float*)d_in[5];
    const float* bq   = (const float*)d_in[6];
    const float* Wk   = (const float*)d_in[7];
    const float* bk   = (const float*)d_in[8];
    const float* Wv   = (const float*)d_in[9];
    const float* bv   = (const float*)d_in[10];
    const float* Wo   = (const float*)d_in[11];
    const float* bo   = (const float*)d_in[12];
    const float* gamma= (const float*)d_in[13];
    const float* beta = (const float*)d_in[14];
    float* out = (float*)d_out;

    cudaFuncSetAttribute(gemm_h,     cudaFuncAttributeMaxDynamicSharedMemorySize, GEMM_SMEM);
    cudaFuncSetAttribute(flash_attn, cudaFuncAttributeMaxDynamicSharedMemorySize, FA_SMEM);

    __half *wt, *x;
    uint32_t *ao;
    cudaGetSymbolAddress((void**)&wt, g_wt);
    cudaGetSymbolAddress((void**)&x,  g_x);
    cudaGetSymbolAddress((void**)&ao, g_ao);

    const size_t WS = (size_t)DM_ * DM_;

    // ---- pre-pass conversions (2 launches) ----
    convert_wt_all<<<dim3(16, 16, 4), 256>>>(Wq, Wk, Wv, Wo, wt);
    convert_x_all<<<18432, 256>>>(Q, K, V, x);

    // ---- projections (fp16 single-pass tensor-core) ----
    gemm_h<<<dim3(8, 16), 256, GEMM_SMEM>>>(x + (size_t)XQ_ROW * DM_, wt + 0 * WS, bq, nullptr, LQ_, 0);
    gemm_h<<<dim3(8, 64), 256, GEMM_SMEM>>>(x + (size_t)XK_ROW * DM_, wt + 1 * WS, bk, nullptr, LK_, 1);
    gemm_h<<<dim3(8, 64), 256, GEMM_SMEM>>>(x + (size_t)XV_ROW * DM_, wt + 2 * WS, bv, nullptr, LK_, 2);

    // ---- attention ----
    flash_attn<<<dim3(LQ_ / 64, H_, B_), 128, FA_SMEM>>>(mask);

    // ---- output projection + residual ----
    gemm_h<<<dim3(8, 16), 256, GEMM_SMEM>>>((const __half*)ao, wt + 3 * WS, bo, Q, LQ_, 3);

    // ---- layernorm ----
    layernorm_kernel<<<B_ * LQ_, 256>>>(gamma, beta, out);
}